// round 1
// baseline (speedup 1.0000x reference)
#include <cuda_runtime.h>

#define SEQ    512
#define HID    768
#define HEADS  12
#define DH     64
#define LAYERS 12
#define BATCH  32
#define ROWS   (BATCH * SEQ)   /* 16384 */
#define LN_EPS 1e-12f

#define TK  16
#define TM  64
#define PAD 68   /* padded shared row for transposed-store gemm tiles */

// Scratch ping-pong buffers (static device globals: allocation-guard safe)
__device__ float g_bufA[(size_t)ROWS * HID];
__device__ float g_bufB[(size_t)ROWS * HID];

// ---------------------------------------------------------------------------
// Embedding lookup + add + LayerNorm.  One block (256 thr) per (batch,seq) row.
// ---------------------------------------------------------------------------
__global__ void __launch_bounds__(256) embed_ln_kernel(
    const int* __restrict__ x,
    const float* __restrict__ we,
    const float* __restrict__ pe,
    const float* __restrict__ te,
    const float* __restrict__ g,
    const float* __restrict__ beta,
    float* __restrict__ out)
{
    int row = blockIdx.x;
    int s   = row & (SEQ - 1);
    int tok = x[row];
    const float* w = we + (size_t)tok * HID;
    const float* p = pe + (size_t)s * HID;

    float v[3];
    float sum = 0.f;
#pragma unroll
    for (int i = 0; i < 3; i++) {
        int c = threadIdx.x + i * 256;
        v[i] = w[c] + p[c] + te[c];
        sum += v[i];
    }

    __shared__ float red[8];
    __shared__ float s_mu, s_rs;

#pragma unroll
    for (int o = 16; o > 0; o >>= 1) sum += __shfl_down_sync(0xffffffffu, sum, o);
    if ((threadIdx.x & 31) == 0) red[threadIdx.x >> 5] = sum;
    __syncthreads();
    if (threadIdx.x == 0) {
        float t = 0.f;
#pragma unroll
        for (int i = 0; i < 8; i++) t += red[i];
        s_mu = t * (1.f / HID);
    }
    __syncthreads();
    float mu = s_mu;

    float sq = 0.f;
#pragma unroll
    for (int i = 0; i < 3; i++) { float d = v[i] - mu; sq += d * d; }
#pragma unroll
    for (int o = 16; o > 0; o >>= 1) sq += __shfl_down_sync(0xffffffffu, sq, o);
    if ((threadIdx.x & 31) == 0) red[threadIdx.x >> 5] = sq;
    __syncthreads();
    if (threadIdx.x == 0) {
        float t = 0.f;
#pragma unroll
        for (int i = 0; i < 8; i++) t += red[i];
        s_rs = rsqrtf(t * (1.f / HID) + LN_EPS);
    }
    __syncthreads();
    float rs = s_rs;

    float* o = out + (size_t)row * HID;
#pragma unroll
    for (int i = 0; i < 3; i++) {
        int c = threadIdx.x + i * 256;
        o[c] = (v[i] - mu) * rs * g[c] + beta[c];
    }
}

// ---------------------------------------------------------------------------
// C[m,n] = sum_k A[m,k] * W[n,k]  (+ optional bias[n]).
// A: [ROWS, HID], W: [HID, HID] row-major (row n holds K).
// Block tile 64x64, K-tile 16, 4x4 per thread, 256 threads.
// ---------------------------------------------------------------------------
__global__ void __launch_bounds__(256) gemm_xwt_kernel(
    const float* __restrict__ A,
    const float* __restrict__ W,
    const float* __restrict__ bias,   // may be null
    float* __restrict__ C)
{
    __shared__ __align__(16) float As[TK][PAD];
    __shared__ __align__(16) float Bs[TK][PAD];

    int tid = threadIdx.x;
    int tx  = tid & 15;
    int ty  = tid >> 4;
    int m0  = blockIdx.y * TM;
    int n0  = blockIdx.x * TM;

    const float* Ab = A + (size_t)m0 * HID;
    const float* Wb = W + (size_t)n0 * HID;

    float acc[4][4] = {};

    for (int k0 = 0; k0 < HID; k0 += TK) {
#pragma unroll
        for (int i = 0; i < 4; i++) {
            int e  = tid + i * 256;
            int mm = e >> 4;
            int kk = e & 15;
            As[kk][mm] = Ab[(size_t)mm * HID + k0 + kk];
            Bs[kk][mm] = Wb[(size_t)mm * HID + k0 + kk];
        }
        __syncthreads();
#pragma unroll
        for (int kk = 0; kk < TK; kk++) {
            float4 a4 = *(const float4*)&As[kk][ty * 4];
            float4 b4 = *(const float4*)&Bs[kk][tx * 4];
            float a[4] = {a4.x, a4.y, a4.z, a4.w};
            float b[4] = {b4.x, b4.y, b4.z, b4.w};
#pragma unroll
            for (int i = 0; i < 4; i++)
#pragma unroll
                for (int j = 0; j < 4; j++)
                    acc[i][j] = fmaf(a[i], b[j], acc[i][j]);
        }
        __syncthreads();
    }

#pragma unroll
    for (int i = 0; i < 4; i++) {
        int m = m0 + ty * 4 + i;
        int n = n0 + tx * 4;
        float4 o4;
        o4.x = acc[i][0]; o4.y = acc[i][1]; o4.z = acc[i][2]; o4.w = acc[i][3];
        if (bias) {
            o4.x += bias[n + 0]; o4.y += bias[n + 1];
            o4.z += bias[n + 2]; o4.w += bias[n + 3];
        }
        *(float4*)&C[(size_t)m * HID + n] = o4;
    }
}

// ---------------------------------------------------------------------------
// Per-(batch, head) sequence mixing: Out[b,t,h*64+d] = relu( sum_s M[h,s,t] *
// T[b,s,h*64+d] + bias[h*64+d] ).  A-side = M^T (contiguous in t), B-side = T
// slice (contiguous in d).  Tile: 64 t x 64 d, K over s.
// ---------------------------------------------------------------------------
__global__ void __launch_bounds__(256) mix_kernel(
    const float* __restrict__ T,     // [B, S, HID]
    const float* __restrict__ Mi,    // [HEADS, SEQ, SEQ]
    const float* __restrict__ bias,  // [HID]
    float* __restrict__ Out)         // [B, S, HID]
{
    __shared__ __align__(16) float Ms[TK][TM];
    __shared__ __align__(16) float Xs[TK][TM];

    int tid = threadIdx.x;
    int tx  = tid & 15;
    int ty  = tid >> 4;
    int t0  = blockIdx.x * TM;
    int h   = blockIdx.y;
    int b   = blockIdx.z;

    const float* Mh = Mi + (size_t)h * SEQ * SEQ;
    const float* Tb = T + (size_t)b * SEQ * HID + h * DH;

    float acc[4][4] = {};

    for (int s0 = 0; s0 < SEQ; s0 += TK) {
#pragma unroll
        for (int i = 0; i < 4; i++) {
            int e  = tid + i * 256;
            int kk = e >> 6;
            int c  = e & 63;
            Ms[kk][c] = Mh[(size_t)(s0 + kk) * SEQ + t0 + c];
            Xs[kk][c] = Tb[(size_t)(s0 + kk) * HID + c];
        }
        __syncthreads();
#pragma unroll
        for (int kk = 0; kk < TK; kk++) {
            float4 a4 = *(const float4*)&Ms[kk][ty * 4];
            float4 b4 = *(const float4*)&Xs[kk][tx * 4];
            float a[4] = {a4.x, a4.y, a4.z, a4.w};
            float bb[4] = {b4.x, b4.y, b4.z, b4.w};
#pragma unroll
            for (int i = 0; i < 4; i++)
#pragma unroll
                for (int j = 0; j < 4; j++)
                    acc[i][j] = fmaf(a[i], bb[j], acc[i][j]);
        }
        __syncthreads();
    }

    int d0 = h * DH + tx * 4;
    float b0 = bias[d0 + 0], b1 = bias[d0 + 1], b2 = bias[d0 + 2], b3 = bias[d0 + 3];
#pragma unroll
    for (int i = 0; i < 4; i++) {
        int t = t0 + ty * 4 + i;
        float4 o4;
        o4.x = fmaxf(acc[i][0] + b0, 0.f);
        o4.y = fmaxf(acc[i][1] + b1, 0.f);
        o4.z = fmaxf(acc[i][2] + b2, 0.f);
        o4.w = fmaxf(acc[i][3] + b3, 0.f);
        *(float4*)&Out[(size_t)b * SEQ * HID + (size_t)t * HID + d0] = o4;
    }
}

// ---------------------------------------------------------------------------
extern "C" void kernel_launch(void* const* d_in, const int* in_sizes, int n_in,
                              void* d_out, int out_size)
{
    const int*   x   = (const int*)d_in[0];
    const float* we  = (const float*)d_in[1];
    const float* pe  = (const float*)d_in[2];
    const float* te  = (const float*)d_in[3];
    const float* lng = (const float*)d_in[4];
    const float* lnb = (const float*)d_in[5];
    const float* W   = (const float*)d_in[6];
    const float* bi  = (const float*)d_in[7];
    const float* Mm  = (const float*)d_in[8];
    const float* lw  = (const float*)d_in[9];
    const float* lb  = (const float*)d_in[10];
    float* out = (float*)d_out;

    float *bufA = nullptr, *bufB = nullptr;
    cudaGetSymbolAddress((void**)&bufA, g_bufA);
    cudaGetSymbolAddress((void**)&bufB, g_bufB);

    embed_ln_kernel<<<ROWS, 256>>>(x, we, pe, te, lng, lnb, bufA);

    dim3 g1(HID / TM, ROWS / TM);       // (12, 256)
    dim3 g2(SEQ / TM, HEADS, BATCH);    // (8, 12, 32)
    for (int l = 0; l < LAYERS; l++) {
        gemm_xwt_kernel<<<g1, 256>>>(bufA, W + (size_t)l * HID * HID, nullptr, bufB);
        mix_kernel<<<g2, 256>>>(bufB, Mm + (size_t)l * HEADS * SEQ * SEQ,
                                bi + (size_t)l * HID, bufA);
    }
    gemm_xwt_kernel<<<g1, 256>>>(bufA, lw, lb, out);
}

// round 3
// speedup vs baseline: 2.5649x; 2.5649x over previous
#include <cuda_runtime.h>
#include <cuda_bf16.h>
#include <stdint.h>

#define SEQ    512
#define HID    768
#define HEADS  12
#define DH     64
#define LAYERS 12
#define BATCH  32
#define ROWS   (BATCH * SEQ)   /* 16384 */
#define LN_EPS 1e-12f

#define KT   32                 /* bf16 k per stage            */
#define RSE  40                 /* smem row stride, elements   */
#define RSB  80                 /* smem row stride, bytes      */
#define BUFB (128 * RSB)        /* one operand buffer: 10240 B */
#define STAGEB (4 * BUFB)       /* Ah,Al,Bh,Bl: 40960 B        */
#define OFF_AH 0
#define OFF_AL (1 * BUFB)
#define OFF_BH (2 * BUFB)
#define OFF_BL (3 * BUFB)
#define SMEM_DYN (2 * STAGEB)   /* 81920 B (>= 128*133*4 epilogue stage) */

/* ------------------------- device scratch (static) ------------------------ */
__device__ __nv_bfloat16 g_hA_hi[(size_t)ROWS * HID];
__device__ __nv_bfloat16 g_hA_lo[(size_t)ROWS * HID];
__device__ __nv_bfloat16 g_Xt_hi[(size_t)ROWS * HID];   /* [B*HEADS*DH][SEQ] */
__device__ __nv_bfloat16 g_Xt_lo[(size_t)ROWS * HID];
__device__ __nv_bfloat16 g_W_hi[(size_t)(LAYERS + 1) * HID * HID];
__device__ __nv_bfloat16 g_W_lo[(size_t)(LAYERS + 1) * HID * HID];
__device__ __nv_bfloat16 g_Mt_hi[(size_t)LAYERS * HEADS * SEQ * SEQ];
__device__ __nv_bfloat16 g_Mt_lo[(size_t)LAYERS * HEADS * SEQ * SEQ];

/* ------------------------------ PTX helpers ------------------------------ */
__device__ __forceinline__ uint32_t smem_u32(const void* p) {
    uint32_t a;
    asm("{ .reg .u64 t; cvta.to.shared.u64 t, %1; cvt.u32.u64 %0, t; }"
        : "=r"(a) : "l"(p));
    return a;
}
__device__ __forceinline__ void cpa16(uint32_t dst, const void* src) {
    asm volatile("cp.async.cg.shared.global [%0], [%1], 16;"
                 :: "r"(dst), "l"(src) : "memory");
}
__device__ __forceinline__ void cp_commit() {
    asm volatile("cp.async.commit_group;" ::: "memory");
}
__device__ __forceinline__ void cp_wait1() {
    asm volatile("cp.async.wait_group 1;" ::: "memory");
}
__device__ __forceinline__ void cp_wait0() {
    asm volatile("cp.async.wait_group 0;" ::: "memory");
}
__device__ __forceinline__ void ldm_x4(uint32_t* r, uint32_t addr) {
    asm volatile("ldmatrix.sync.aligned.m8n8.x4.shared.b16 {%0,%1,%2,%3}, [%4];"
                 : "=r"(r[0]), "=r"(r[1]), "=r"(r[2]), "=r"(r[3]) : "r"(addr));
}
__device__ __forceinline__ void mma16816(float* c, const uint32_t* a, const uint32_t* b) {
    asm volatile(
        "mma.sync.aligned.m16n8k16.row.col.f32.bf16.bf16.f32 "
        "{%0,%1,%2,%3},{%4,%5,%6,%7},{%8,%9},{%0,%1,%2,%3};"
        : "+f"(c[0]), "+f"(c[1]), "+f"(c[2]), "+f"(c[3])
        : "r"(a[0]), "r"(a[1]), "r"(a[2]), "r"(a[3]), "r"(b[0]), "r"(b[1]));
}

/* ------------------------------ stage loaders ----------------------------- */
/* 2048 16B chunks per stage; 8 per thread.  buf = i>>1 (compile-time). */
__device__ __forceinline__ void stage_load_dense(
    uint32_t sm, const __nv_bfloat16* Ah, const __nv_bfloat16* Al,
    const __nv_bfloat16* Wh, const __nv_bfloat16* Wl, int m0, int n0, int k0)
{
    int tid = threadIdx.x;
#pragma unroll
    for (int i = 0; i < 8; i++) {
        const int buf = i >> 1;
        int rem = tid + (i & 1) * 256;
        int row = rem >> 2;
        int c   = rem & 3;
        const __nv_bfloat16* src;
        if      (buf == 0) src = Ah + (size_t)(m0 + row) * HID + k0 + c * 8;
        else if (buf == 1) src = Al + (size_t)(m0 + row) * HID + k0 + c * 8;
        else if (buf == 2) src = Wh + (size_t)(n0 + row) * HID + k0 + c * 8;
        else               src = Wl + (size_t)(n0 + row) * HID + k0 + c * 8;
        cpa16(sm + buf * BUFB + row * RSB + c * 16, src);
    }
}
__device__ __forceinline__ void stage_load_mix(
    uint32_t sm, const __nv_bfloat16* Mh, const __nv_bfloat16* Ml,
    const __nv_bfloat16* Xh, const __nv_bfloat16* Xl,
    int t0, int h, int b0, int s0)
{
    int tid = threadIdx.x;
#pragma unroll
    for (int i = 0; i < 8; i++) {
        const int buf = i >> 1;
        int rem = tid + (i & 1) * 256;
        int row = rem >> 2;
        int c   = rem & 3;
        const __nv_bfloat16* src;
        if (buf < 2) {
            const __nv_bfloat16* M = (buf == 0) ? Mh : Ml;
            src = M + (size_t)(t0 + row) * SEQ + s0 + c * 8;
        } else {
            const __nv_bfloat16* X = (buf == 2) ? Xh : Xl;
            int bb = row >> 6, d = row & 63;
            size_t R = ((size_t)(b0 + bb) * HEADS + h) * DH + d;
            src = X + R * SEQ + s0 + c * 8;
        }
        cpa16(sm + buf * BUFB + row * RSB + c * 16, src);
    }
}

/* ------------------------------- MMA core -------------------------------- */
__device__ __forceinline__ void compute_ktile(
    uint32_t sbase, float (*acc)[4], int wm, int wn, int lane)
{
    const int ar = lane & 15;
    const int ac = (lane >> 4) * 8;
    const int br = ((lane >> 4) << 3) + (lane & 7);
    const int bc = ((lane >> 3) & 1) * 8;
#pragma unroll
    for (int ks = 0; ks < 2; ks++) {
        uint32_t ah[8], al[8];
#pragma unroll
        for (int mi = 0; mi < 2; mi++) {
            uint32_t off = ((wm * 32 + mi * 16 + ar) * RSE + ks * 16 + ac) * 2;
            ldm_x4(ah + 4 * mi, sbase + OFF_AH + off);
            ldm_x4(al + 4 * mi, sbase + OFF_AL + off);
        }
#pragma unroll
        for (int nh = 0; nh < 2; nh++) {
            uint32_t bh[8], bl[8];
#pragma unroll
            for (int g = 0; g < 2; g++) {
                uint32_t off = ((wn * 64 + nh * 32 + g * 16 + br) * RSE + ks * 16 + bc) * 2;
                ldm_x4(bh + 4 * g, sbase + OFF_BH + off);
                ldm_x4(bl + 4 * g, sbase + OFF_BL + off);
            }
#pragma unroll
            for (int pass = 0; pass < 3; pass++) {
                const uint32_t* A = (pass == 2) ? al : ah;
                const uint32_t* B = (pass == 1) ? bl : bh;
#pragma unroll
                for (int mi = 0; mi < 2; mi++)
#pragma unroll
                    for (int nj = 0; nj < 4; nj++)
                        mma16816(acc[mi * 8 + nh * 4 + nj], A + 4 * mi, B + 2 * nj);
            }
        }
    }
}

/* dump acc tile into padded f32 smem stage [128][133] */
__device__ __forceinline__ void acc_to_stage(
    float* stage, float (*acc)[4], int wm, int wn, int lane)
{
#pragma unroll
    for (int mi = 0; mi < 2; mi++)
#pragma unroll
        for (int nj = 0; nj < 8; nj++) {
            int r  = wm * 32 + mi * 16 + (lane >> 2);
            int cn = wn * 64 + nj * 8 + (lane & 3) * 2;
            float* p = stage + r * 133 + cn;
            p[0] = acc[mi * 8 + nj][0];
            p[1] = acc[mi * 8 + nj][1];
            p += 8 * 133;
            p[0] = acc[mi * 8 + nj][2];
            p[1] = acc[mi * 8 + nj][3];
        }
}

/* --------------------------- dense tensor GEMM ---------------------------- */
/* D[m,n] = sum_k A[m,k]*W[n,k].
   FINAL=false: write split bf16 TRANSPOSED into Xt[(b*HEADS+h)*DH+d][s].
   FINAL=true : write f32 + bias row-major to Of. */
template <bool FINAL>
__global__ void __launch_bounds__(256, 2) gemm_dense_kernel(
    const __nv_bfloat16* __restrict__ Ah, const __nv_bfloat16* __restrict__ Al,
    const __nv_bfloat16* __restrict__ Wh, const __nv_bfloat16* __restrict__ Wl,
    const float* __restrict__ bias,
    __nv_bfloat16* __restrict__ Ohi, __nv_bfloat16* __restrict__ Olo,
    float* __restrict__ Of)
{
    extern __shared__ __align__(16) char smem[];
    uint32_t sb = smem_u32(smem);
    int tid = threadIdx.x, lane = tid & 31, wid = tid >> 5;
    int wm = wid & 3, wn = wid >> 2;
    int n0 = blockIdx.x * 128, m0 = blockIdx.y * 128;

    float acc[16][4];
#pragma unroll
    for (int i = 0; i < 16; i++)
#pragma unroll
        for (int j = 0; j < 4; j++) acc[i][j] = 0.f;

    const int NK = HID / KT;   /* 24 */
    stage_load_dense(sb, Ah, Al, Wh, Wl, m0, n0, 0);  cp_commit();
    stage_load_dense(sb + STAGEB, Ah, Al, Wh, Wl, m0, n0, KT);  cp_commit();

    for (int i = 0; i < NK; i++) {
        if (i + 1 < NK) cp_wait1(); else cp_wait0();
        __syncthreads();
        compute_ktile(sb + (i & 1) * STAGEB, acc, wm, wn, lane);
        __syncthreads();
        if (i + 2 < NK) {
            stage_load_dense(sb + (i & 1) * STAGEB, Ah, Al, Wh, Wl, m0, n0, (i + 2) * KT);
            cp_commit();
        }
    }

    float* stage = (float*)smem;
    acc_to_stage(stage, acc, wm, wn, lane);
    __syncthreads();

    if (!FINAL) {
        /* transposed split write: thread -> one n-row, half the s range */
        int n  = tid >> 1, sh = tid & 1;
        int ng = n0 + n;
        int h  = ng >> 6, d = ng & 63;
        int b  = m0 >> 9;
        int s  = (m0 & 511) + sh * 64;
        size_t R = ((size_t)b * HEADS + h) * DH + d;
        __nv_bfloat16* dh = Ohi + R * SEQ + s;
        __nv_bfloat16* dl = Olo + R * SEQ + s;
#pragma unroll
        for (int q = 0; q < 8; q++) {
            __align__(16) __nv_bfloat16 hv[8], lv[8];
#pragma unroll
            for (int j = 0; j < 8; j++) {
                float v = stage[(sh * 64 + q * 8 + j) * 133 + n];
                __nv_bfloat16 hb = __float2bfloat16(v);
                hv[j] = hb;
                lv[j] = __float2bfloat16(v - __bfloat162float(hb));
            }
            *(uint4*)(dh + q * 8) = *(const uint4*)hv;
            *(uint4*)(dl + q * 8) = *(const uint4*)lv;
        }
    } else {
        int m = tid >> 1, half = tid & 1;
        float* dst = Of + (size_t)(m0 + m) * HID + n0 + half * 64;
        const float* bp = bias + n0 + half * 64;
#pragma unroll
        for (int q = 0; q < 16; q++) {
            __align__(16) float ov[4];
#pragma unroll
            for (int j = 0; j < 4; j++)
                ov[j] = stage[m * 133 + half * 64 + q * 4 + j] + bp[q * 4 + j];
            *(uint4*)(dst + q * 4) = *(const uint4*)ov;
        }
    }
}

/* ---------------------------- mix tensor GEMM ----------------------------- */
/* Out[b0+bb, t0+t, h*64+d] = relu( sum_s Mt[h,t,s] * X[b,s,h*64+d] + bias ),
   A = Mt (row-major t x s), B = Xt[(b*HEADS+h)*DH+d][s] (row-major n x s). */
__global__ void __launch_bounds__(256, 2) gemm_mix_kernel(
    const __nv_bfloat16* __restrict__ Xh, const __nv_bfloat16* __restrict__ Xl,
    const __nv_bfloat16* __restrict__ Mth, const __nv_bfloat16* __restrict__ Mtl,
    const float* __restrict__ bias,
    __nv_bfloat16* __restrict__ Ohi, __nv_bfloat16* __restrict__ Olo)
{
    extern __shared__ __align__(16) char smem[];
    uint32_t sb = smem_u32(smem);
    int tid = threadIdx.x, lane = tid & 31, wid = tid >> 5;
    int wm = wid & 3, wn = wid >> 2;
    int t0 = blockIdx.x * 128;
    int h  = blockIdx.y;
    int b0 = blockIdx.z * 2;

    const __nv_bfloat16* Mh = Mth + (size_t)h * SEQ * SEQ;
    const __nv_bfloat16* Ml = Mtl + (size_t)h * SEQ * SEQ;

    float acc[16][4];
#pragma unroll
    for (int i = 0; i < 16; i++)
#pragma unroll
        for (int j = 0; j < 4; j++) acc[i][j] = 0.f;

    const int NK = SEQ / KT;   /* 16 */
    stage_load_mix(sb, Mh, Ml, Xh, Xl, t0, h, b0, 0);  cp_commit();
    stage_load_mix(sb + STAGEB, Mh, Ml, Xh, Xl, t0, h, b0, KT);  cp_commit();

    for (int i = 0; i < NK; i++) {
        if (i + 1 < NK) cp_wait1(); else cp_wait0();
        __syncthreads();
        compute_ktile(sb + (i & 1) * STAGEB, acc, wm, wn, lane);
        __syncthreads();
        if (i + 2 < NK) {
            stage_load_mix(sb + (i & 1) * STAGEB, Mh, Ml, Xh, Xl, t0, h, b0, (i + 2) * KT);
            cp_commit();
        }
    }

    float* stage = (float*)smem;
    acc_to_stage(stage, acc, wm, wn, lane);
    __syncthreads();

    /* bias + relu + split, write row-major hA */
    int m = tid >> 1, half = tid & 1;   /* half == bb */
    size_t row = (size_t)(b0 + half) * SEQ + t0 + m;
    __nv_bfloat16* dh = Ohi + row * HID + h * DH;
    __nv_bfloat16* dl = Olo + row * HID + h * DH;
    const float* bp = bias + h * DH;
#pragma unroll
    for (int q = 0; q < 8; q++) {
        __align__(16) __nv_bfloat16 hv[8], lv[8];
#pragma unroll
        for (int j = 0; j < 8; j++) {
            float v = stage[m * 133 + half * 64 + q * 8 + j] + bp[q * 8 + j];
            v = fmaxf(v, 0.f);
            __nv_bfloat16 hb = __float2bfloat16(v);
            hv[j] = hb;
            lv[j] = __float2bfloat16(v - __bfloat162float(hb));
        }
        *(uint4*)(dh + q * 8) = *(const uint4*)hv;
        *(uint4*)(dl + q * 8) = *(const uint4*)lv;
    }
}

/* --------------------------- conversion kernels --------------------------- */
__global__ void __launch_bounds__(256) split_kernel(
    const float* __restrict__ s, __nv_bfloat16* __restrict__ dh,
    __nv_bfloat16* __restrict__ dl, int n)
{
    for (int i = blockIdx.x * 256 + threadIdx.x; i < n; i += gridDim.x * 256) {
        float v = s[i];
        __nv_bfloat16 hb = __float2bfloat16(v);
        dh[i] = hb;
        dl[i] = __float2bfloat16(v - __bfloat162float(hb));
    }
}

/* Mt[l,h,t,s] = M[l,h,s,t]; tiled 32x32 transpose + split */
__global__ void __launch_bounds__(256) transpose_split_kernel(
    const float* __restrict__ M, __nv_bfloat16* __restrict__ th,
    __nv_bfloat16* __restrict__ tl)
{
    __shared__ float tile[32][33];
    const float* src = M + (size_t)blockIdx.z * SEQ * SEQ;
    int s0 = blockIdx.x * 32, t0 = blockIdx.y * 32;
    int tx = threadIdx.x, ty = threadIdx.y;
#pragma unroll
    for (int i = ty; i < 32; i += 8)
        tile[i][tx] = src[(size_t)(s0 + i) * SEQ + t0 + tx];
    __syncthreads();
    size_t ob = (size_t)blockIdx.z * SEQ * SEQ;
#pragma unroll
    for (int i = ty; i < 32; i += 8) {
        float v = tile[tx][i];
        __nv_bfloat16 hb = __float2bfloat16(v);
        size_t o = ob + (size_t)(t0 + i) * SEQ + s0 + tx;
        th[o] = hb;
        tl[o] = __float2bfloat16(v - __bfloat162float(hb));
    }
}

__global__ void __launch_bounds__(256) embed_ln_split_kernel(
    const int* __restrict__ x,
    const float* __restrict__ we, const float* __restrict__ pe,
    const float* __restrict__ te,
    const float* __restrict__ g, const float* __restrict__ beta,
    __nv_bfloat16* __restrict__ ohi, __nv_bfloat16* __restrict__ olo)
{
    int row = blockIdx.x;
    int s   = row & (SEQ - 1);
    int tok = x[row];
    const float* w = we + (size_t)tok * HID;
    const float* p = pe + (size_t)s * HID;

    float v[3];
    float sum = 0.f;
#pragma unroll
    for (int i = 0; i < 3; i++) {
        int c = threadIdx.x + i * 256;
        v[i] = w[c] + p[c] + te[c];
        sum += v[i];
    }

    __shared__ float red[8];
    __shared__ float s_mu, s_rs;
#pragma unroll
    for (int o = 16; o > 0; o >>= 1) sum += __shfl_down_sync(0xffffffffu, sum, o);
    if ((threadIdx.x & 31) == 0) red[threadIdx.x >> 5] = sum;
    __syncthreads();
    if (threadIdx.x == 0) {
        float t = 0.f;
#pragma unroll
        for (int i = 0; i < 8; i++) t += red[i];
        s_mu = t * (1.f / HID);
    }
    __syncthreads();
    float mu = s_mu;

    float sq = 0.f;
#pragma unroll
    for (int i = 0; i < 3; i++) { float d = v[i] - mu; sq += d * d; }
#pragma unroll
    for (int o = 16; o > 0; o >>= 1) sq += __shfl_down_sync(0xffffffffu, sq, o);
    if ((threadIdx.x & 31) == 0) red[threadIdx.x >> 5] = sq;
    __syncthreads();
    if (threadIdx.x == 0) {
        float t = 0.f;
#pragma unroll
        for (int i = 0; i < 8; i++) t += red[i];
        s_rs = rsqrtf(t * (1.f / HID) + LN_EPS);
    }
    __syncthreads();
    float rs = s_rs;

#pragma unroll
    for (int i = 0; i < 3; i++) {
        int c = threadIdx.x + i * 256;
        float val = (v[i] - mu) * rs * g[c] + beta[c];
        __nv_bfloat16 hb = __float2bfloat16(val);
        ohi[(size_t)row * HID + c] = hb;
        olo[(size_t)row * HID + c] = __float2bfloat16(val - __bfloat162float(hb));
    }
}

/* --------------------------------- launch --------------------------------- */
extern "C" void kernel_launch(void* const* d_in, const int* in_sizes, int n_in,
                              void* d_out, int out_size)
{
    const int*   x   = (const int*)d_in[0];
    const float* we  = (const float*)d_in[1];
    const float* pe  = (const float*)d_in[2];
    const float* te  = (const float*)d_in[3];
    const float* lng = (const float*)d_in[4];
    const float* lnb = (const float*)d_in[5];
    const float* W   = (const float*)d_in[6];
    const float* bi  = (const float*)d_in[7];
    const float* Mm  = (const float*)d_in[8];
    const float* lw  = (const float*)d_in[9];
    const float* lb  = (const float*)d_in[10];
    float* out = (float*)d_out;

    __nv_bfloat16 *hAh, *hAl, *Xth, *Xtl, *Wh, *Wl, *Mth, *Mtl;
    cudaGetSymbolAddress((void**)&hAh, g_hA_hi);
    cudaGetSymbolAddress((void**)&hAl, g_hA_lo);
    cudaGetSymbolAddress((void**)&Xth, g_Xt_hi);
    cudaGetSymbolAddress((void**)&Xtl, g_Xt_lo);
    cudaGetSymbolAddress((void**)&Wh,  g_W_hi);
    cudaGetSymbolAddress((void**)&Wl,  g_W_lo);
    cudaGetSymbolAddress((void**)&Mth, g_Mt_hi);
    cudaGetSymbolAddress((void**)&Mtl, g_Mt_lo);

    cudaFuncSetAttribute(gemm_dense_kernel<false>,
                         cudaFuncAttributeMaxDynamicSharedMemorySize, SMEM_DYN);
    cudaFuncSetAttribute(gemm_dense_kernel<true>,
                         cudaFuncAttributeMaxDynamicSharedMemorySize, SMEM_DYN);
    cudaFuncSetAttribute(gemm_mix_kernel,
                         cudaFuncAttributeMaxDynamicSharedMemorySize, SMEM_DYN);

    /* one-time conversions */
    embed_ln_split_kernel<<<ROWS, 256>>>(x, we, pe, te, lng, lnb, hAh, hAl);
    split_kernel<<<2048, 256>>>(W, Wh, Wl, LAYERS * HID * HID);
    split_kernel<<<256, 256>>>(lw, Wh + (size_t)LAYERS * HID * HID,
                               Wl + (size_t)LAYERS * HID * HID, HID * HID);
    {
        dim3 tb(32, 8), tg(SEQ / 32, SEQ / 32, LAYERS * HEADS);
        transpose_split_kernel<<<tg, tb>>>(Mm, Mth, Mtl);
    }

    dim3 gd(HID / 128, ROWS / 128);       /* (6, 128)    */
    dim3 gm(SEQ / 128, HEADS, BATCH / 2); /* (4, 12, 16) */
    for (int l = 0; l < LAYERS; l++) {
        gemm_dense_kernel<false><<<gd, 256, SMEM_DYN>>>(
            hAh, hAl,
            Wh + (size_t)l * HID * HID, Wl + (size_t)l * HID * HID,
            nullptr, Xth, Xtl, nullptr);
        gemm_mix_kernel<<<gm, 256, SMEM_DYN>>>(
            Xth, Xtl,
            Mth + (size_t)l * HEADS * SEQ * SEQ,
            Mtl + (size_t)l * HEADS * SEQ * SEQ,
            bi + (size_t)l * HID, hAh, hAl);
    }
    gemm_dense_kernel<true><<<gd, 256, SMEM_DYN>>>(
        hAh, hAl,
        Wh + (size_t)LAYERS * HID * HID, Wl + (size_t)LAYERS * HID * HID,
        lb, nullptr, nullptr, out);
}

// round 4
// speedup vs baseline: 2.6209x; 1.0218x over previous
#include <cuda_runtime.h>
#include <cuda_bf16.h>
#include <stdint.h>

#define SEQ    512
#define HID    768
#define HEADS  12
#define DH     64
#define LAYERS 12
#define BATCH  32
#define ROWS   (BATCH * SEQ)   /* 16384 */
#define LN_EPS 1e-12f

#define KT   32                 /* bf16 k per stage            */
#define RSE  40                 /* smem row stride, elements   */
#define RSB  80                 /* smem row stride, bytes      */
#define BUFB (128 * RSB)        /* one operand buffer: 10240 B */
#define STAGEB (4 * BUFB)       /* Ah,Al,Bh,Bl: 40960 B        */
#define OFF_AH 0
#define OFF_AL (1 * BUFB)
#define OFF_BH (2 * BUFB)
#define OFF_BL (3 * BUFB)
#define SMEM_DYN (2 * STAGEB)   /* 81920 B (>= 128*133*4 epilogue stage) */

/* ------------------------- device scratch (static) ------------------------ */
__device__ __nv_bfloat16 g_hA_hi[(size_t)ROWS * HID];
__device__ __nv_bfloat16 g_hA_lo[(size_t)ROWS * HID];
__device__ __nv_bfloat16 g_Xt_hi[(size_t)ROWS * HID];   /* [B*HEADS*DH][SEQ] */
__device__ __nv_bfloat16 g_Xt_lo[(size_t)ROWS * HID];
__device__ __nv_bfloat16 g_W_hi[(size_t)(LAYERS + 1) * HID * HID];
__device__ __nv_bfloat16 g_W_lo[(size_t)(LAYERS + 1) * HID * HID];
__device__ __nv_bfloat16 g_Mt_hi[(size_t)LAYERS * HEADS * SEQ * SEQ];
__device__ __nv_bfloat16 g_Mt_lo[(size_t)LAYERS * HEADS * SEQ * SEQ];

/* ------------------------------ PTX helpers ------------------------------ */
__device__ __forceinline__ uint32_t smem_u32(const void* p) {
    uint32_t a;
    asm("{ .reg .u64 t; cvta.to.shared.u64 t, %1; cvt.u32.u64 %0, t; }"
        : "=r"(a) : "l"(p));
    return a;
}
__device__ __forceinline__ void cpa16(uint32_t dst, const void* src) {
    asm volatile("cp.async.cg.shared.global [%0], [%1], 16;"
                 :: "r"(dst), "l"(src) : "memory");
}
__device__ __forceinline__ void cp_commit() {
    asm volatile("cp.async.commit_group;" ::: "memory");
}
__device__ __forceinline__ void cp_wait1() {
    asm volatile("cp.async.wait_group 1;" ::: "memory");
}
__device__ __forceinline__ void cp_wait0() {
    asm volatile("cp.async.wait_group 0;" ::: "memory");
}
__device__ __forceinline__ void ldm_x4(uint32_t* r, uint32_t addr) {
    asm volatile("ldmatrix.sync.aligned.m8n8.x4.shared.b16 {%0,%1,%2,%3}, [%4];"
                 : "=r"(r[0]), "=r"(r[1]), "=r"(r[2]), "=r"(r[3]) : "r"(addr));
}
__device__ __forceinline__ void mma16816(float* c, const uint32_t* a, const uint32_t* b) {
    asm volatile(
        "mma.sync.aligned.m16n8k16.row.col.f32.bf16.bf16.f32 "
        "{%0,%1,%2,%3},{%4,%5,%6,%7},{%8,%9},{%0,%1,%2,%3};"
        : "+f"(c[0]), "+f"(c[1]), "+f"(c[2]), "+f"(c[3])
        : "r"(a[0]), "r"(a[1]), "r"(a[2]), "r"(a[3]), "r"(b[0]), "r"(b[1]));
}

/* ------------------------------ stage loaders ----------------------------- */
/* 2048 16B chunks per stage; 16 per thread (128 threads). buf = i>>2. */
__device__ __forceinline__ void stage_load_dense(
    uint32_t sm, const __nv_bfloat16* Ah, const __nv_bfloat16* Al,
    const __nv_bfloat16* Wh, const __nv_bfloat16* Wl, int m0, int n0, int k0)
{
    int tid = threadIdx.x;
#pragma unroll
    for (int i = 0; i < 16; i++) {
        const int buf = i >> 2;
        int rem = tid + (i & 3) * 128;
        int row = rem >> 2;
        int c   = rem & 3;
        const __nv_bfloat16* src;
        if      (buf == 0) src = Ah + (size_t)(m0 + row) * HID + k0 + c * 8;
        else if (buf == 1) src = Al + (size_t)(m0 + row) * HID + k0 + c * 8;
        else if (buf == 2) src = Wh + (size_t)(n0 + row) * HID + k0 + c * 8;
        else               src = Wl + (size_t)(n0 + row) * HID + k0 + c * 8;
        cpa16(sm + buf * BUFB + row * RSB + c * 16, src);
    }
}
__device__ __forceinline__ void stage_load_mix(
    uint32_t sm, const __nv_bfloat16* Mh, const __nv_bfloat16* Ml,
    const __nv_bfloat16* Xh, const __nv_bfloat16* Xl,
    int t0, int h, int b0, int s0)
{
    int tid = threadIdx.x;
#pragma unroll
    for (int i = 0; i < 16; i++) {
        const int buf = i >> 2;
        int rem = tid + (i & 3) * 128;
        int row = rem >> 2;
        int c   = rem & 3;
        const __nv_bfloat16* src;
        if (buf < 2) {
            const __nv_bfloat16* M = (buf == 0) ? Mh : Ml;
            src = M + (size_t)(t0 + row) * SEQ + s0 + c * 8;
        } else {
            const __nv_bfloat16* X = (buf == 2) ? Xh : Xl;
            int bb = row >> 6, d = row & 63;
            size_t R = ((size_t)(b0 + bb) * HEADS + h) * DH + d;
            src = X + R * SEQ + s0 + c * 8;
        }
        cpa16(sm + buf * BUFB + row * RSB + c * 16, src);
    }
}

/* ------------------------------- MMA core -------------------------------- */
/* 4 warps, each computes a 64m x 64n tile; acc[32][4]. */
__device__ __forceinline__ void compute_ktile(
    uint32_t sbase, float (*acc)[4], int wm, int wn, int lane)
{
    const int ar = lane & 15;
    const int ac = (lane >> 4) * 8;
    const int br = ((lane >> 4) << 3) + (lane & 7);
    const int bc = ((lane >> 3) & 1) * 8;
#pragma unroll
    for (int ks = 0; ks < 2; ks++) {
        uint32_t ah[16], al[16];
#pragma unroll
        for (int mi = 0; mi < 4; mi++) {
            uint32_t off = ((wm * 64 + mi * 16 + ar) * RSE + ks * 16 + ac) * 2;
            ldm_x4(ah + 4 * mi, sbase + OFF_AH + off);
            ldm_x4(al + 4 * mi, sbase + OFF_AL + off);
        }
#pragma unroll
        for (int nh = 0; nh < 2; nh++) {
            uint32_t bh[8], bl[8];
#pragma unroll
            for (int g = 0; g < 2; g++) {
                uint32_t off = ((wn * 64 + nh * 32 + g * 16 + br) * RSE + ks * 16 + bc) * 2;
                ldm_x4(bh + 4 * g, sbase + OFF_BH + off);
                ldm_x4(bl + 4 * g, sbase + OFF_BL + off);
            }
#pragma unroll
            for (int pass = 0; pass < 3; pass++) {
                const uint32_t* A = (pass == 2) ? al : ah;
                const uint32_t* B = (pass == 1) ? bl : bh;
#pragma unroll
                for (int mi = 0; mi < 4; mi++)
#pragma unroll
                    for (int nj = 0; nj < 4; nj++)
                        mma16816(acc[mi * 8 + nh * 4 + nj], A + 4 * mi, B + 2 * nj);
            }
        }
    }
}

/* dump acc tile into padded f32 smem stage [128][133] */
__device__ __forceinline__ void acc_to_stage(
    float* stage, float (*acc)[4], int wm, int wn, int lane)
{
#pragma unroll
    for (int mi = 0; mi < 4; mi++)
#pragma unroll
        for (int nj = 0; nj < 8; nj++) {
            int r  = wm * 64 + mi * 16 + (lane >> 2);
            int cn = wn * 64 + nj * 8 + (lane & 3) * 2;
            float* p = stage + r * 133 + cn;
            p[0] = acc[mi * 8 + nj][0];
            p[1] = acc[mi * 8 + nj][1];
            p += 8 * 133;
            p[0] = acc[mi * 8 + nj][2];
            p[1] = acc[mi * 8 + nj][3];
        }
}

/* --------------------------- dense tensor GEMM ---------------------------- */
/* D[m,n] = sum_k A[m,k]*W[n,k].
   FINAL=false: write split bf16 TRANSPOSED into Xt[(b*HEADS+h)*DH+d][s].
   FINAL=true : write f32 + bias row-major to Of. */
template <bool FINAL>
__global__ void __launch_bounds__(128, 2) gemm_dense_kernel(
    const __nv_bfloat16* __restrict__ Ah, const __nv_bfloat16* __restrict__ Al,
    const __nv_bfloat16* __restrict__ Wh, const __nv_bfloat16* __restrict__ Wl,
    const float* __restrict__ bias,
    __nv_bfloat16* __restrict__ Ohi, __nv_bfloat16* __restrict__ Olo,
    float* __restrict__ Of)
{
    extern __shared__ __align__(16) char smem[];
    uint32_t sb = smem_u32(smem);
    int tid = threadIdx.x, lane = tid & 31, wid = tid >> 5;
    int wm = wid & 1, wn = wid >> 1;
    int n0 = blockIdx.x * 128, m0 = blockIdx.y * 128;

    float acc[32][4];
#pragma unroll
    for (int i = 0; i < 32; i++)
#pragma unroll
        for (int j = 0; j < 4; j++) acc[i][j] = 0.f;

    const int NK = HID / KT;   /* 24 */
    stage_load_dense(sb, Ah, Al, Wh, Wl, m0, n0, 0);  cp_commit();
    stage_load_dense(sb + STAGEB, Ah, Al, Wh, Wl, m0, n0, KT);  cp_commit();

    for (int i = 0; i < NK; i++) {
        if (i + 1 < NK) cp_wait1(); else cp_wait0();
        __syncthreads();
        compute_ktile(sb + (i & 1) * STAGEB, acc, wm, wn, lane);
        __syncthreads();
        if (i + 2 < NK) {
            stage_load_dense(sb + (i & 1) * STAGEB, Ah, Al, Wh, Wl, m0, n0, (i + 2) * KT);
            cp_commit();
        }
    }

    float* stage = (float*)smem;
    acc_to_stage(stage, acc, wm, wn, lane);
    __syncthreads();

    if (!FINAL) {
        /* transposed split write: thread -> one n-row, all 128 s */
        int n  = tid;
        int ng = n0 + n;
        int h  = ng >> 6, d = ng & 63;
        int b  = m0 >> 9;
        int s  = m0 & 511;
        size_t R = ((size_t)b * HEADS + h) * DH + d;
        __nv_bfloat16* dh = Ohi + R * SEQ + s;
        __nv_bfloat16* dl = Olo + R * SEQ + s;
#pragma unroll
        for (int q = 0; q < 16; q++) {
            __align__(16) __nv_bfloat16 hv[8], lv[8];
#pragma unroll
            for (int j = 0; j < 8; j++) {
                float v = stage[(q * 8 + j) * 133 + n];
                __nv_bfloat16 hb = __float2bfloat16(v);
                hv[j] = hb;
                lv[j] = __float2bfloat16(v - __bfloat162float(hb));
            }
            *(uint4*)(dh + q * 8) = *(const uint4*)hv;
            *(uint4*)(dl + q * 8) = *(const uint4*)lv;
        }
    } else {
        int m = tid;
        float* dst = Of + (size_t)(m0 + m) * HID + n0;
        const float* bp = bias + n0;
#pragma unroll
        for (int q = 0; q < 32; q++) {
            __align__(16) float ov[4];
#pragma unroll
            for (int j = 0; j < 4; j++)
                ov[j] = stage[m * 133 + q * 4 + j] + bp[q * 4 + j];
            *(uint4*)(dst + q * 4) = *(const uint4*)ov;
        }
    }
}

/* ---------------------------- mix tensor GEMM ----------------------------- */
/* Out[b0+bb, t0+t, h*64+d] = relu( sum_s Mt[h,t,s] * X[b,s,h*64+d] + bias ),
   A = Mt (row-major t x s), B = Xt[(b*HEADS+h)*DH+d][s] (row-major n x s). */
__global__ void __launch_bounds__(128, 2) gemm_mix_kernel(
    const __nv_bfloat16* __restrict__ Xh, const __nv_bfloat16* __restrict__ Xl,
    const __nv_bfloat16* __restrict__ Mth, const __nv_bfloat16* __restrict__ Mtl,
    const float* __restrict__ bias,
    __nv_bfloat16* __restrict__ Ohi, __nv_bfloat16* __restrict__ Olo)
{
    extern __shared__ __align__(16) char smem[];
    uint32_t sb = smem_u32(smem);
    int tid = threadIdx.x, lane = tid & 31, wid = tid >> 5;
    int wm = wid & 1, wn = wid >> 1;
    int t0 = blockIdx.x * 128;
    int h  = blockIdx.y;
    int b0 = blockIdx.z * 2;

    const __nv_bfloat16* Mh = Mth + (size_t)h * SEQ * SEQ;
    const __nv_bfloat16* Ml = Mtl + (size_t)h * SEQ * SEQ;

    float acc[32][4];
#pragma unroll
    for (int i = 0; i < 32; i++)
#pragma unroll
        for (int j = 0; j < 4; j++) acc[i][j] = 0.f;

    const int NK = SEQ / KT;   /* 16 */
    stage_load_mix(sb, Mh, Ml, Xh, Xl, t0, h, b0, 0);  cp_commit();
    stage_load_mix(sb + STAGEB, Mh, Ml, Xh, Xl, t0, h, b0, KT);  cp_commit();

    for (int i = 0; i < NK; i++) {
        if (i + 1 < NK) cp_wait1(); else cp_wait0();
        __syncthreads();
        compute_ktile(sb + (i & 1) * STAGEB, acc, wm, wn, lane);
        __syncthreads();
        if (i + 2 < NK) {
            stage_load_mix(sb + (i & 1) * STAGEB, Mh, Ml, Xh, Xl, t0, h, b0, (i + 2) * KT);
            cp_commit();
        }
    }

    float* stage = (float*)smem;
    acc_to_stage(stage, acc, wm, wn, lane);
    __syncthreads();

    /* bias + relu + split, write row-major hA; thread = one t, both bb */
    int m = tid;
#pragma unroll
    for (int half = 0; half < 2; half++) {
        size_t row = (size_t)(b0 + half) * SEQ + t0 + m;
        __nv_bfloat16* dh = Ohi + row * HID + h * DH;
        __nv_bfloat16* dl = Olo + row * HID + h * DH;
        const float* bp = bias + h * DH;
#pragma unroll
        for (int q = 0; q < 8; q++) {
            __align__(16) __nv_bfloat16 hv[8], lv[8];
#pragma unroll
            for (int j = 0; j < 8; j++) {
                float v = stage[m * 133 + half * 64 + q * 8 + j] + bp[q * 8 + j];
                v = fmaxf(v, 0.f);
                __nv_bfloat16 hb = __float2bfloat16(v);
                hv[j] = hb;
                lv[j] = __float2bfloat16(v - __bfloat162float(hb));
            }
            *(uint4*)(dh + q * 8) = *(const uint4*)hv;
            *(uint4*)(dl + q * 8) = *(const uint4*)lv;
        }
    }
}

/* --------------------------- conversion kernels --------------------------- */
__global__ void __launch_bounds__(256) split_kernel(
    const float* __restrict__ s, __nv_bfloat16* __restrict__ dh,
    __nv_bfloat16* __restrict__ dl, int n)
{
    for (int i = blockIdx.x * 256 + threadIdx.x; i < n; i += gridDim.x * 256) {
        float v = s[i];
        __nv_bfloat16 hb = __float2bfloat16(v);
        dh[i] = hb;
        dl[i] = __float2bfloat16(v - __bfloat162float(hb));
    }
}

/* Mt[l,h,t,s] = M[l,h,s,t]; tiled 32x32 transpose + split */
__global__ void __launch_bounds__(256) transpose_split_kernel(
    const float* __restrict__ M, __nv_bfloat16* __restrict__ th,
    __nv_bfloat16* __restrict__ tl)
{
    __shared__ float tile[32][33];
    const float* src = M + (size_t)blockIdx.z * SEQ * SEQ;
    int s0 = blockIdx.x * 32, t0 = blockIdx.y * 32;
    int tx = threadIdx.x, ty = threadIdx.y;
#pragma unroll
    for (int i = ty; i < 32; i += 8)
        tile[i][tx] = src[(size_t)(s0 + i) * SEQ + t0 + tx];
    __syncthreads();
    size_t ob = (size_t)blockIdx.z * SEQ * SEQ;
#pragma unroll
    for (int i = ty; i < 32; i += 8) {
        float v = tile[tx][i];
        __nv_bfloat16 hb = __float2bfloat16(v);
        size_t o = ob + (size_t)(t0 + i) * SEQ + s0 + tx;
        th[o] = hb;
        tl[o] = __float2bfloat16(v - __bfloat162float(hb));
    }
}

__global__ void __launch_bounds__(256) embed_ln_split_kernel(
    const int* __restrict__ x,
    const float* __restrict__ we, const float* __restrict__ pe,
    const float* __restrict__ te,
    const float* __restrict__ g, const float* __restrict__ beta,
    __nv_bfloat16* __restrict__ ohi, __nv_bfloat16* __restrict__ olo)
{
    int row = blockIdx.x;
    int s   = row & (SEQ - 1);
    int tok = x[row];
    const float* w = we + (size_t)tok * HID;
    const float* p = pe + (size_t)s * HID;

    float v[3];
    float sum = 0.f;
#pragma unroll
    for (int i = 0; i < 3; i++) {
        int c = threadIdx.x + i * 256;
        v[i] = w[c] + p[c] + te[c];
        sum += v[i];
    }

    __shared__ float red[8];
    __shared__ float s_mu, s_rs;
#pragma unroll
    for (int o = 16; o > 0; o >>= 1) sum += __shfl_down_sync(0xffffffffu, sum, o);
    if ((threadIdx.x & 31) == 0) red[threadIdx.x >> 5] = sum;
    __syncthreads();
    if (threadIdx.x == 0) {
        float t = 0.f;
#pragma unroll
        for (int i = 0; i < 8; i++) t += red[i];
        s_mu = t * (1.f / HID);
    }
    __syncthreads();
    float mu = s_mu;

    float sq = 0.f;
#pragma unroll
    for (int i = 0; i < 3; i++) { float d = v[i] - mu; sq += d * d; }
#pragma unroll
    for (int o = 16; o > 0; o >>= 1) sq += __shfl_down_sync(0xffffffffu, sq, o);
    if ((threadIdx.x & 31) == 0) red[threadIdx.x >> 5] = sq;
    __syncthreads();
    if (threadIdx.x == 0) {
        float t = 0.f;
#pragma unroll
        for (int i = 0; i < 8; i++) t += red[i];
        s_rs = rsqrtf(t * (1.f / HID) + LN_EPS);
    }
    __syncthreads();
    float rs = s_rs;

#pragma unroll
    for (int i = 0; i < 3; i++) {
        int c = threadIdx.x + i * 256;
        float val = (v[i] - mu) * rs * g[c] + beta[c];
        __nv_bfloat16 hb = __float2bfloat16(val);
        ohi[(size_t)row * HID + c] = hb;
        olo[(size_t)row * HID + c] = __float2bfloat16(val - __bfloat162float(hb));
    }
}

/* --------------------------------- launch --------------------------------- */
extern "C" void kernel_launch(void* const* d_in, const int* in_sizes, int n_in,
                              void* d_out, int out_size)
{
    const int*   x   = (const int*)d_in[0];
    const float* we  = (const float*)d_in[1];
    const float* pe  = (const float*)d_in[2];
    const float* te  = (const float*)d_in[3];
    const float* lng = (const float*)d_in[4];
    const float* lnb = (const float*)d_in[5];
    const float* W   = (const float*)d_in[6];
    const float* bi  = (const float*)d_in[7];
    const float* Mm  = (const float*)d_in[8];
    const float* lw  = (const float*)d_in[9];
    const float* lb  = (const float*)d_in[10];
    float* out = (float*)d_out;

    __nv_bfloat16 *hAh, *hAl, *Xth, *Xtl, *Wh, *Wl, *Mth, *Mtl;
    cudaGetSymbolAddress((void**)&hAh, g_hA_hi);
    cudaGetSymbolAddress((void**)&hAl, g_hA_lo);
    cudaGetSymbolAddress((void**)&Xth, g_Xt_hi);
    cudaGetSymbolAddress((void**)&Xtl, g_Xt_lo);
    cudaGetSymbolAddress((void**)&Wh,  g_W_hi);
    cudaGetSymbolAddress((void**)&Wl,  g_W_lo);
    cudaGetSymbolAddress((void**)&Mth, g_Mt_hi);
    cudaGetSymbolAddress((void**)&Mtl, g_Mt_lo);

    cudaFuncSetAttribute(gemm_dense_kernel<false>,
                         cudaFuncAttributeMaxDynamicSharedMemorySize, SMEM_DYN);
    cudaFuncSetAttribute(gemm_dense_kernel<true>,
                         cudaFuncAttributeMaxDynamicSharedMemorySize, SMEM_DYN);
    cudaFuncSetAttribute(gemm_mix_kernel,
                         cudaFuncAttributeMaxDynamicSharedMemorySize, SMEM_DYN);

    /* one-time conversions */
    embed_ln_split_kernel<<<ROWS, 256>>>(x, we, pe, te, lng, lnb, hAh, hAl);
    split_kernel<<<2048, 256>>>(W, Wh, Wl, LAYERS * HID * HID);
    split_kernel<<<256, 256>>>(lw, Wh + (size_t)LAYERS * HID * HID,
                               Wl + (size_t)LAYERS * HID * HID, HID * HID);
    {
        dim3 tb(32, 8), tg(SEQ / 32, SEQ / 32, LAYERS * HEADS);
        transpose_split_kernel<<<tg, tb>>>(Mm, Mth, Mtl);
    }

    dim3 gd(HID / 128, ROWS / 128);       /* (6, 128)    */
    dim3 gm(SEQ / 128, HEADS, BATCH / 2); /* (4, 12, 16) */
    for (int l = 0; l < LAYERS; l++) {
        gemm_dense_kernel<false><<<gd, 128, SMEM_DYN>>>(
            hAh, hAl,
            Wh + (size_t)l * HID * HID, Wl + (size_t)l * HID * HID,
            nullptr, Xth, Xtl, nullptr);
        gemm_mix_kernel<<<gm, 128, SMEM_DYN>>>(
            Xth, Xtl,
            Mth + (size_t)l * HEADS * SEQ * SEQ,
            Mtl + (size_t)l * HEADS * SEQ * SEQ,
            bi + (size_t)l * HID, hAh, hAl);
    }
    gemm_dense_kernel<true><<<gd, 128, SMEM_DYN>>>(
        hAh, hAl,
        Wh + (size_t)LAYERS * HID * HID, Wl + (size_t)LAYERS * HID * HID,
        lb, nullptr, nullptr, out);
}

// round 5
// speedup vs baseline: 3.6235x; 1.3825x over previous
#include <cuda_runtime.h>
#include <cuda_fp16.h>
#include <stdint.h>

#define SEQ    512
#define HID    768
#define HEADS  12
#define DH     64
#define LAYERS 12
#define BATCH  32
#define ROWS   (BATCH * SEQ)   /* 16384 */
#define LN_EPS 1e-12f

#define KT   32                 /* fp16 k per stage            */
#define RSE  40                 /* smem row stride, elements   */
#define RSB  80                 /* smem row stride, bytes      */
#define BUFB (128 * RSB)        /* one operand buffer: 10240 B */
#define STAGEB (3 * BUFB)       /* Ah, Al, Bh: 30720 B         */
#define NSTAGE 3
#define OFF_AH 0
#define OFF_AL (1 * BUFB)
#define OFF_BH (2 * BUFB)
#define SMEM_DYN (NSTAGE * STAGEB)   /* 92160 B (>= 128*133*4 epilogue) */

/* ------------------------- device scratch (static) ------------------------ */
__device__ __half g_hA_hi[(size_t)ROWS * HID];
__device__ __half g_hA_lo[(size_t)ROWS * HID];
__device__ __half g_Xt_hi[(size_t)ROWS * HID];   /* [B*HEADS*DH][SEQ] */
__device__ __half g_W_hi[(size_t)(LAYERS + 1) * HID * HID];
__device__ __half g_Mt_hi[(size_t)LAYERS * HEADS * SEQ * SEQ];
__device__ __half g_Mt_lo[(size_t)LAYERS * HEADS * SEQ * SEQ];

/* ------------------------------ PTX helpers ------------------------------ */
__device__ __forceinline__ uint32_t smem_u32(const void* p) {
    uint32_t a;
    asm("{ .reg .u64 t; cvta.to.shared.u64 t, %1; cvt.u32.u64 %0, t; }"
        : "=r"(a) : "l"(p));
    return a;
}
__device__ __forceinline__ void cpa16(uint32_t dst, const void* src) {
    asm volatile("cp.async.cg.shared.global [%0], [%1], 16;"
                 :: "r"(dst), "l"(src) : "memory");
}
__device__ __forceinline__ void cp_commit() {
    asm volatile("cp.async.commit_group;" ::: "memory");
}
__device__ __forceinline__ void cp_wait1() {
    asm volatile("cp.async.wait_group 1;" ::: "memory");
}
__device__ __forceinline__ void cp_wait0() {
    asm volatile("cp.async.wait_group 0;" ::: "memory");
}
__device__ __forceinline__ void ldm_x4(uint32_t* r, uint32_t addr) {
    asm volatile("ldmatrix.sync.aligned.m8n8.x4.shared.b16 {%0,%1,%2,%3}, [%4];"
                 : "=r"(r[0]), "=r"(r[1]), "=r"(r[2]), "=r"(r[3]) : "r"(addr));
}
__device__ __forceinline__ void mma16816(float* c, const uint32_t* a, const uint32_t* b) {
    asm volatile(
        "mma.sync.aligned.m16n8k16.row.col.f32.f16.f16.f32 "
        "{%0,%1,%2,%3},{%4,%5,%6,%7},{%8,%9},{%0,%1,%2,%3};"
        : "+f"(c[0]), "+f"(c[1]), "+f"(c[2]), "+f"(c[3])
        : "r"(a[0]), "r"(a[1]), "r"(a[2]), "r"(a[3]), "r"(b[0]), "r"(b[1]));
}
__device__ __forceinline__ void split_h(float v, __half& hi, __half& lo) {
    hi = __float2half_rn(v);
    lo = __float2half_rn(v - __half2float(hi));
}

/* ------------------------------ stage loaders ----------------------------- */
/* 3 buffers x 512 16B chunks; 12 per thread (128 threads). buf = i>>2. */
__device__ __forceinline__ void stage_load_dense(
    uint32_t sm, const __half* Ah, const __half* Al,
    const __half* Wh, int m0, int n0, int k0)
{
    int tid = threadIdx.x;
#pragma unroll
    for (int i = 0; i < 12; i++) {
        const int buf = i >> 2;
        int rem = tid + (i & 3) * 128;
        int row = rem >> 2;
        int c   = rem & 3;
        const __half* src;
        if      (buf == 0) src = Ah + (size_t)(m0 + row) * HID + k0 + c * 8;
        else if (buf == 1) src = Al + (size_t)(m0 + row) * HID + k0 + c * 8;
        else               src = Wh + (size_t)(n0 + row) * HID + k0 + c * 8;
        cpa16(sm + buf * BUFB + row * RSB + c * 16, src);
    }
}
__device__ __forceinline__ void stage_load_mix(
    uint32_t sm, const __half* Mh, const __half* Ml,
    const __half* Xh, int t0, int h, int b0, int s0)
{
    int tid = threadIdx.x;
#pragma unroll
    for (int i = 0; i < 12; i++) {
        const int buf = i >> 2;
        int rem = tid + (i & 3) * 128;
        int row = rem >> 2;
        int c   = rem & 3;
        const __half* src;
        if (buf < 2) {
            const __half* M = (buf == 0) ? Mh : Ml;
            src = M + (size_t)(t0 + row) * SEQ + s0 + c * 8;
        } else {
            int bb = row >> 6, d = row & 63;
            size_t R = ((size_t)(b0 + bb) * HEADS + h) * DH + d;
            src = Xh + R * SEQ + s0 + c * 8;
        }
        cpa16(sm + buf * BUFB + row * RSB + c * 16, src);
    }
}

/* ------------------------------- MMA core -------------------------------- */
/* 4 warps, each computes a 64m x 64n tile; acc[32][4]. 2 passes: AhBh+AlBh. */
__device__ __forceinline__ void compute_ktile(
    uint32_t sbase, float (*acc)[4], int wm, int wn, int lane)
{
    const int ar = lane & 15;
    const int ac = (lane >> 4) * 8;
    const int br = ((lane >> 4) << 3) + (lane & 7);
    const int bc = ((lane >> 3) & 1) * 8;
#pragma unroll
    for (int ks = 0; ks < 2; ks++) {
        uint32_t ah[16], al[16];
#pragma unroll
        for (int mi = 0; mi < 4; mi++) {
            uint32_t off = ((wm * 64 + mi * 16 + ar) * RSE + ks * 16 + ac) * 2;
            ldm_x4(ah + 4 * mi, sbase + OFF_AH + off);
            ldm_x4(al + 4 * mi, sbase + OFF_AL + off);
        }
#pragma unroll
        for (int nh = 0; nh < 2; nh++) {
            uint32_t bh[8];
#pragma unroll
            for (int g = 0; g < 2; g++) {
                uint32_t off = ((wn * 64 + nh * 32 + g * 16 + br) * RSE + ks * 16 + bc) * 2;
                ldm_x4(bh + 4 * g, sbase + OFF_BH + off);
            }
#pragma unroll
            for (int pass = 0; pass < 2; pass++) {
                const uint32_t* A = pass ? al : ah;
#pragma unroll
                for (int mi = 0; mi < 4; mi++)
#pragma unroll
                    for (int nj = 0; nj < 4; nj++)
                        mma16816(acc[mi * 8 + nh * 4 + nj], A + 4 * mi, bh + 2 * nj);
            }
        }
    }
}

/* dump acc tile into padded f32 smem stage [128][133] */
__device__ __forceinline__ void acc_to_stage(
    float* stage, float (*acc)[4], int wm, int wn, int lane)
{
#pragma unroll
    for (int mi = 0; mi < 4; mi++)
#pragma unroll
        for (int nj = 0; nj < 8; nj++) {
            int r  = wm * 64 + mi * 16 + (lane >> 2);
            int cn = wn * 64 + nj * 8 + (lane & 3) * 2;
            float* p = stage + r * 133 + cn;
            p[0] = acc[mi * 8 + nj][0];
            p[1] = acc[mi * 8 + nj][1];
            p += 8 * 133;
            p[0] = acc[mi * 8 + nj][2];
            p[1] = acc[mi * 8 + nj][3];
        }
}

/* --------------------------- dense tensor GEMM ---------------------------- */
/* D[m,n] = sum_k A[m,k]*W[n,k].
   FINAL=false: write hi-only fp16 TRANSPOSED into Xt[(b*HEADS+h)*DH+d][s].
   FINAL=true : write f32 + bias row-major to Of. */
template <bool FINAL>
__global__ void __launch_bounds__(128, 2) gemm_dense_kernel(
    const __half* __restrict__ Ah, const __half* __restrict__ Al,
    const __half* __restrict__ Wh,
    const float* __restrict__ bias,
    __half* __restrict__ Ohi,
    float* __restrict__ Of)
{
    extern __shared__ __align__(16) char smem[];
    uint32_t sb = smem_u32(smem);
    int tid = threadIdx.x, lane = tid & 31, wid = tid >> 5;
    int wm = wid & 1, wn = wid >> 1;
    int n0 = blockIdx.x * 128, m0 = blockIdx.y * 128;

    float acc[32][4];
#pragma unroll
    for (int i = 0; i < 32; i++)
#pragma unroll
        for (int j = 0; j < 4; j++) acc[i][j] = 0.f;

    const int NK = HID / KT;   /* 24 */
    stage_load_dense(sb, Ah, Al, Wh, m0, n0, 0);           cp_commit();
    stage_load_dense(sb + STAGEB, Ah, Al, Wh, m0, n0, KT); cp_commit();

    for (int i = 0; i < NK; i++) {
        if (i + 1 < NK) cp_wait1(); else cp_wait0();
        __syncthreads();
        if (i + 2 < NK) {
            stage_load_dense(sb + ((i + 2) % NSTAGE) * STAGEB, Ah, Al, Wh, m0, n0, (i + 2) * KT);
            cp_commit();
        }
        compute_ktile(sb + (i % NSTAGE) * STAGEB, acc, wm, wn, lane);
    }
    __syncthreads();

    float* stage = (float*)smem;
    acc_to_stage(stage, acc, wm, wn, lane);
    __syncthreads();

    if (!FINAL) {
        /* transposed hi-only write: thread -> one n-row, all 128 s */
        int n  = tid;
        int ng = n0 + n;
        int h  = ng >> 6, d = ng & 63;
        int b  = m0 >> 9;
        int s  = m0 & 511;
        size_t R = ((size_t)b * HEADS + h) * DH + d;
        __half* dh = Ohi + R * SEQ + s;
#pragma unroll
        for (int q = 0; q < 16; q++) {
            __align__(16) __half hv[8];
#pragma unroll
            for (int j = 0; j < 8; j++)
                hv[j] = __float2half_rn(stage[(q * 8 + j) * 133 + n]);
            *(uint4*)(dh + q * 8) = *(const uint4*)hv;
        }
    } else {
        int m = tid;
        float* dst = Of + (size_t)(m0 + m) * HID + n0;
        const float* bp = bias + n0;
#pragma unroll
        for (int q = 0; q < 32; q++) {
            __align__(16) float ov[4];
#pragma unroll
            for (int j = 0; j < 4; j++)
                ov[j] = stage[m * 133 + q * 4 + j] + bp[q * 4 + j];
            *(uint4*)(dst + q * 4) = *(const uint4*)ov;
        }
    }
}

/* ---------------------------- mix tensor GEMM ----------------------------- */
/* Out[b0+bb, t0+t, h*64+d] = relu( sum_s Mt[h,t,s] * X[b,s,h*64+d] + bias ),
   A = Mt hi/lo (row-major t x s), B = Xt hi (row-major n x s). */
__global__ void __launch_bounds__(128, 2) gemm_mix_kernel(
    const __half* __restrict__ Xh,
    const __half* __restrict__ Mth, const __half* __restrict__ Mtl,
    const float* __restrict__ bias,
    __half* __restrict__ Ohi, __half* __restrict__ Olo)
{
    extern __shared__ __align__(16) char smem[];
    uint32_t sb = smem_u32(smem);
    int tid = threadIdx.x, lane = tid & 31, wid = tid >> 5;
    int wm = wid & 1, wn = wid >> 1;
    int t0 = blockIdx.x * 128;
    int h  = blockIdx.y;
    int b0 = blockIdx.z * 2;

    const __half* Mh = Mth + (size_t)h * SEQ * SEQ;
    const __half* Ml = Mtl + (size_t)h * SEQ * SEQ;

    float acc[32][4];
#pragma unroll
    for (int i = 0; i < 32; i++)
#pragma unroll
        for (int j = 0; j < 4; j++) acc[i][j] = 0.f;

    const int NK = SEQ / KT;   /* 16 */
    stage_load_mix(sb, Mh, Ml, Xh, t0, h, b0, 0);           cp_commit();
    stage_load_mix(sb + STAGEB, Mh, Ml, Xh, t0, h, b0, KT); cp_commit();

    for (int i = 0; i < NK; i++) {
        if (i + 1 < NK) cp_wait1(); else cp_wait0();
        __syncthreads();
        if (i + 2 < NK) {
            stage_load_mix(sb + ((i + 2) % NSTAGE) * STAGEB, Mh, Ml, Xh, t0, h, b0, (i + 2) * KT);
            cp_commit();
        }
        compute_ktile(sb + (i % NSTAGE) * STAGEB, acc, wm, wn, lane);
    }
    __syncthreads();

    float* stage = (float*)smem;
    acc_to_stage(stage, acc, wm, wn, lane);
    __syncthreads();

    /* bias + relu + split, write row-major hA; thread = one t, both bb */
    int m = tid;
#pragma unroll
    for (int half = 0; half < 2; half++) {
        size_t row = (size_t)(b0 + half) * SEQ + t0 + m;
        __half* dh = Ohi + row * HID + h * DH;
        __half* dl = Olo + row * HID + h * DH;
        const float* bp = bias + h * DH;
#pragma unroll
        for (int q = 0; q < 8; q++) {
            __align__(16) __half hv[8], lv[8];
#pragma unroll
            for (int j = 0; j < 8; j++) {
                float v = stage[m * 133 + half * 64 + q * 8 + j] + bp[q * 8 + j];
                v = fmaxf(v, 0.f);
                split_h(v, hv[j], lv[j]);
            }
            *(uint4*)(dh + q * 8) = *(const uint4*)hv;
            *(uint4*)(dl + q * 8) = *(const uint4*)lv;
        }
    }
}

/* --------------------------- conversion kernels --------------------------- */
__global__ void __launch_bounds__(256) cvt_hi_kernel(
    const float* __restrict__ s, __half* __restrict__ dh, int n)
{
    for (int i = blockIdx.x * 256 + threadIdx.x; i < n; i += gridDim.x * 256)
        dh[i] = __float2half_rn(s[i]);
}

/* Mt[l,h,t,s] = M[l,h,s,t]; tiled 32x32 transpose + fp16 hi/lo split */
__global__ void __launch_bounds__(256) transpose_split_kernel(
    const float* __restrict__ M, __half* __restrict__ th, __half* __restrict__ tl)
{
    __shared__ float tile[32][33];
    const float* src = M + (size_t)blockIdx.z * SEQ * SEQ;
    int s0 = blockIdx.x * 32, t0 = blockIdx.y * 32;
    int tx = threadIdx.x, ty = threadIdx.y;
#pragma unroll
    for (int i = ty; i < 32; i += 8)
        tile[i][tx] = src[(size_t)(s0 + i) * SEQ + t0 + tx];
    __syncthreads();
    size_t ob = (size_t)blockIdx.z * SEQ * SEQ;
#pragma unroll
    for (int i = ty; i < 32; i += 8) {
        size_t o = ob + (size_t)(t0 + i) * SEQ + s0 + tx;
        __half hb, lb2;
        split_h(tile[tx][i], hb, lb2);
        th[o] = hb;
        tl[o] = lb2;
    }
}

__global__ void __launch_bounds__(256) embed_ln_split_kernel(
    const int* __restrict__ x,
    const float* __restrict__ we, const float* __restrict__ pe,
    const float* __restrict__ te,
    const float* __restrict__ g, const float* __restrict__ beta,
    __half* __restrict__ ohi, __half* __restrict__ olo)
{
    int row = blockIdx.x;
    int s   = row & (SEQ - 1);
    int tok = x[row];
    const float* w = we + (size_t)tok * HID;
    const float* p = pe + (size_t)s * HID;

    float v[3];
    float sum = 0.f;
#pragma unroll
    for (int i = 0; i < 3; i++) {
        int c = threadIdx.x + i * 256;
        v[i] = w[c] + p[c] + te[c];
        sum += v[i];
    }

    __shared__ float red[8];
    __shared__ float s_mu, s_rs;
#pragma unroll
    for (int o = 16; o > 0; o >>= 1) sum += __shfl_down_sync(0xffffffffu, sum, o);
    if ((threadIdx.x & 31) == 0) red[threadIdx.x >> 5] = sum;
    __syncthreads();
    if (threadIdx.x == 0) {
        float t = 0.f;
#pragma unroll
        for (int i = 0; i < 8; i++) t += red[i];
        s_mu = t * (1.f / HID);
    }
    __syncthreads();
    float mu = s_mu;

    float sq = 0.f;
#pragma unroll
    for (int i = 0; i < 3; i++) { float d = v[i] - mu; sq += d * d; }
#pragma unroll
    for (int o = 16; o > 0; o >>= 1) sq += __shfl_down_sync(0xffffffffu, sq, o);
    if ((threadIdx.x & 31) == 0) red[threadIdx.x >> 5] = sq;
    __syncthreads();
    if (threadIdx.x == 0) {
        float t = 0.f;
#pragma unroll
        for (int i = 0; i < 8; i++) t += red[i];
        s_rs = rsqrtf(t * (1.f / HID) + LN_EPS);
    }
    __syncthreads();
    float rs = s_rs;

#pragma unroll
    for (int i = 0; i < 3; i++) {
        int c = threadIdx.x + i * 256;
        float val = (v[i] - mu) * rs * g[c] + beta[c];
        __half hb, lb2;
        split_h(val, hb, lb2);
        ohi[(size_t)row * HID + c] = hb;
        olo[(size_t)row * HID + c] = lb2;
    }
}

/* --------------------------------- launch --------------------------------- */
extern "C" void kernel_launch(void* const* d_in, const int* in_sizes, int n_in,
                              void* d_out, int out_size)
{
    const int*   x   = (const int*)d_in[0];
    const float* we  = (const float*)d_in[1];
    const float* pe  = (const float*)d_in[2];
    const float* te  = (const float*)d_in[3];
    const float* lng = (const float*)d_in[4];
    const float* lnb = (const float*)d_in[5];
    const float* W   = (const float*)d_in[6];
    const float* bi  = (const float*)d_in[7];
    const float* Mm  = (const float*)d_in[8];
    const float* lw  = (const float*)d_in[9];
    const float* lb  = (const float*)d_in[10];
    float* out = (float*)d_out;

    __half *hAh, *hAl, *Xth, *Wh, *Mth, *Mtl;
    cudaGetSymbolAddress((void**)&hAh, g_hA_hi);
    cudaGetSymbolAddress((void**)&hAl, g_hA_lo);
    cudaGetSymbolAddress((void**)&Xth, g_Xt_hi);
    cudaGetSymbolAddress((void**)&Wh,  g_W_hi);
    cudaGetSymbolAddress((void**)&Mth, g_Mt_hi);
    cudaGetSymbolAddress((void**)&Mtl, g_Mt_lo);

    cudaFuncSetAttribute(gemm_dense_kernel<false>,
                         cudaFuncAttributeMaxDynamicSharedMemorySize, SMEM_DYN);
    cudaFuncSetAttribute(gemm_dense_kernel<true>,
                         cudaFuncAttributeMaxDynamicSharedMemorySize, SMEM_DYN);
    cudaFuncSetAttribute(gemm_mix_kernel,
                         cudaFuncAttributeMaxDynamicSharedMemorySize, SMEM_DYN);

    /* one-time conversions */
    embed_ln_split_kernel<<<ROWS, 256>>>(x, we, pe, te, lng, lnb, hAh, hAl);
    cvt_hi_kernel<<<2048, 256>>>(W, Wh, LAYERS * HID * HID);
    cvt_hi_kernel<<<256, 256>>>(lw, Wh + (size_t)LAYERS * HID * HID, HID * HID);
    {
        dim3 tb(32, 8), tg(SEQ / 32, SEQ / 32, LAYERS * HEADS);
        transpose_split_kernel<<<tg, tb>>>(Mm, Mth, Mtl);
    }

    dim3 gd(HID / 128, ROWS / 128);       /* (6, 128)    */
    dim3 gm(SEQ / 128, HEADS, BATCH / 2); /* (4, 12, 16) */
    for (int l = 0; l < LAYERS; l++) {
        gemm_dense_kernel<false><<<gd, 128, SMEM_DYN>>>(
            hAh, hAl, Wh + (size_t)l * HID * HID,
            nullptr, Xth, nullptr);
        gemm_mix_kernel<<<gm, 128, SMEM_DYN>>>(
            Xth,
            Mth + (size_t)l * HEADS * SEQ * SEQ,
            Mtl + (size_t)l * HEADS * SEQ * SEQ,
            bi + (size_t)l * HID, hAh, hAl);
    }
    gemm_dense_kernel<true><<<gd, 128, SMEM_DYN>>>(
        hAh, hAl, Wh + (size_t)LAYERS * HID * HID,
        lb, nullptr, out);
}

// round 6
// speedup vs baseline: 6.4257x; 1.7733x over previous
#include <cuda_runtime.h>
#include <cuda_fp16.h>
#include <stdint.h>

#define SEQ    512
#define HID    768
#define HEADS  12
#define DH     64
#define LAYERS 12
#define BATCH  32
#define ROWS   (BATCH * SEQ)   /* 16384 */
#define LN_EPS 1e-12f

#define KT   32                 /* fp16 k per stage            */
#define RSE  40                 /* smem row stride, elements   */
#define RSB  80                 /* smem row stride, bytes      */
#define BUFB (128 * RSB)        /* one operand buffer: 10240 B */
#define STAGEB (2 * BUFB)       /* A, B: 20480 B               */
#define NSTAGE 4
#define OFF_A 0
#define OFF_B BUFB
#define SMEM_DYN (NSTAGE * STAGEB)   /* 81920 B (>= 128*133*4 epilogue) */

/* ------------------------- device scratch (static) ------------------------ */
__device__ __half g_hA[(size_t)ROWS * HID];
__device__ __half g_Xt[(size_t)ROWS * HID];   /* [B*HEADS*DH][SEQ] */
__device__ __half g_W[(size_t)(LAYERS + 1) * HID * HID];
__device__ __half g_Mt[(size_t)LAYERS * HEADS * SEQ * SEQ];

/* ------------------------------ PTX helpers ------------------------------ */
__device__ __forceinline__ uint32_t smem_u32(const void* p) {
    uint32_t a;
    asm("{ .reg .u64 t; cvta.to.shared.u64 t, %1; cvt.u32.u64 %0, t; }"
        : "=r"(a) : "l"(p));
    return a;
}
__device__ __forceinline__ void cpa16(uint32_t dst, const void* src) {
    asm volatile("cp.async.cg.shared.global [%0], [%1], 16;"
                 :: "r"(dst), "l"(src) : "memory");
}
__device__ __forceinline__ void cp_commit() {
    asm volatile("cp.async.commit_group;" ::: "memory");
}
__device__ __forceinline__ void cp_wait2() {
    asm volatile("cp.async.wait_group 2;" ::: "memory");
}
__device__ __forceinline__ void cp_wait0() {
    asm volatile("cp.async.wait_group 0;" ::: "memory");
}
__device__ __forceinline__ void ldm_x4(uint32_t* r, uint32_t addr) {
    asm volatile("ldmatrix.sync.aligned.m8n8.x4.shared.b16 {%0,%1,%2,%3}, [%4];"
                 : "=r"(r[0]), "=r"(r[1]), "=r"(r[2]), "=r"(r[3]) : "r"(addr));
}
__device__ __forceinline__ void mma16816(float* c, const uint32_t* a, const uint32_t* b) {
    asm volatile(
        "mma.sync.aligned.m16n8k16.row.col.f32.f16.f16.f32 "
        "{%0,%1,%2,%3},{%4,%5,%6,%7},{%8,%9},{%0,%1,%2,%3};"
        : "+f"(c[0]), "+f"(c[1]), "+f"(c[2]), "+f"(c[3])
        : "r"(a[0]), "r"(a[1]), "r"(a[2]), "r"(a[3]), "r"(b[0]), "r"(b[1]));
}

/* ------------------------------ stage loaders ----------------------------- */
/* 2 buffers x 512 16B chunks; 8 per thread (128 threads). buf = i>>2. */
__device__ __forceinline__ void stage_load_dense(
    uint32_t sm, const __half* A, const __half* W, int m0, int n0, int k0)
{
    int tid = threadIdx.x;
#pragma unroll
    for (int i = 0; i < 8; i++) {
        const int buf = i >> 2;
        int rem = tid + (i & 3) * 128;
        int row = rem >> 2;
        int c   = rem & 3;
        const __half* src = buf
            ? W + (size_t)(n0 + row) * HID + k0 + c * 8
            : A + (size_t)(m0 + row) * HID + k0 + c * 8;
        cpa16(sm + buf * BUFB + row * RSB + c * 16, src);
    }
}
__device__ __forceinline__ void stage_load_mix(
    uint32_t sm, const __half* M, const __half* X,
    int t0, int h, int b0, int s0)
{
    int tid = threadIdx.x;
#pragma unroll
    for (int i = 0; i < 8; i++) {
        const int buf = i >> 2;
        int rem = tid + (i & 3) * 128;
        int row = rem >> 2;
        int c   = rem & 3;
        const __half* src;
        if (buf == 0) {
            src = M + (size_t)(t0 + row) * SEQ + s0 + c * 8;
        } else {
            int bb = row >> 6, d = row & 63;
            size_t R = ((size_t)(b0 + bb) * HEADS + h) * DH + d;
            src = X + R * SEQ + s0 + c * 8;
        }
        cpa16(sm + buf * BUFB + row * RSB + c * 16, src);
    }
}

/* ------------------------------- MMA core -------------------------------- */
/* 4 warps, each computes a 64m x 64n tile; acc[32][4]. Single fp16 pass. */
__device__ __forceinline__ void compute_ktile(
    uint32_t sbase, float (*acc)[4], int wm, int wn, int lane)
{
    const int ar = lane & 15;
    const int ac = (lane >> 4) * 8;
    const int br = ((lane >> 4) << 3) + (lane & 7);
    const int bc = ((lane >> 3) & 1) * 8;
#pragma unroll
    for (int ks = 0; ks < 2; ks++) {
        uint32_t af[16];
#pragma unroll
        for (int mi = 0; mi < 4; mi++) {
            uint32_t off = ((wm * 64 + mi * 16 + ar) * RSE + ks * 16 + ac) * 2;
            ldm_x4(af + 4 * mi, sbase + OFF_A + off);
        }
#pragma unroll
        for (int nh = 0; nh < 2; nh++) {
            uint32_t bf[8];
#pragma unroll
            for (int g = 0; g < 2; g++) {
                uint32_t off = ((wn * 64 + nh * 32 + g * 16 + br) * RSE + ks * 16 + bc) * 2;
                ldm_x4(bf + 4 * g, sbase + OFF_B + off);
            }
#pragma unroll
            for (int mi = 0; mi < 4; mi++)
#pragma unroll
                for (int nj = 0; nj < 4; nj++)
                    mma16816(acc[mi * 8 + nh * 4 + nj], af + 4 * mi, bf + 2 * nj);
        }
    }
}

/* dump acc tile into padded f32 smem stage [128][133] */
__device__ __forceinline__ void acc_to_stage(
    float* stage, float (*acc)[4], int wm, int wn, int lane)
{
#pragma unroll
    for (int mi = 0; mi < 4; mi++)
#pragma unroll
        for (int nj = 0; nj < 8; nj++) {
            int r  = wm * 64 + mi * 16 + (lane >> 2);
            int cn = wn * 64 + nj * 8 + (lane & 3) * 2;
            float* p = stage + r * 133 + cn;
            p[0] = acc[mi * 8 + nj][0];
            p[1] = acc[mi * 8 + nj][1];
            p += 8 * 133;
            p[0] = acc[mi * 8 + nj][2];
            p[1] = acc[mi * 8 + nj][3];
        }
}

/* --------------------------- dense tensor GEMM ---------------------------- */
/* D[m,n] = sum_k A[m,k]*W[n,k].
   FINAL=false: write fp16 TRANSPOSED into Xt[(b*HEADS+h)*DH+d][s].
   FINAL=true : write f32 + bias row-major to Of. */
template <bool FINAL>
__global__ void __launch_bounds__(128, 2) gemm_dense_kernel(
    const __half* __restrict__ A, const __half* __restrict__ W,
    const float* __restrict__ bias,
    __half* __restrict__ Oh, float* __restrict__ Of)
{
    extern __shared__ __align__(16) char smem[];
    uint32_t sb = smem_u32(smem);
    int tid = threadIdx.x, lane = tid & 31, wid = tid >> 5;
    int wm = wid & 1, wn = wid >> 1;
    int n0 = blockIdx.x * 128, m0 = blockIdx.y * 128;

    float acc[32][4];
#pragma unroll
    for (int i = 0; i < 32; i++)
#pragma unroll
        for (int j = 0; j < 4; j++) acc[i][j] = 0.f;

    const int NK = HID / KT;   /* 24 */
    stage_load_dense(sb,              A, W, m0, n0, 0);      cp_commit();
    stage_load_dense(sb + STAGEB,     A, W, m0, n0, KT);     cp_commit();
    stage_load_dense(sb + 2 * STAGEB, A, W, m0, n0, 2 * KT); cp_commit();

    for (int i = 0; i < NK; i++) {
        if (i + 1 < NK) cp_wait2(); else cp_wait0();
        __syncthreads();
        if (i + 3 < NK) {
            stage_load_dense(sb + ((i + 3) % NSTAGE) * STAGEB, A, W, m0, n0, (i + 3) * KT);
            cp_commit();
        }
        compute_ktile(sb + (i % NSTAGE) * STAGEB, acc, wm, wn, lane);
    }
    __syncthreads();

    float* stage = (float*)smem;
    acc_to_stage(stage, acc, wm, wn, lane);
    __syncthreads();

    if (!FINAL) {
        /* transposed fp16 write: thread -> one n-row, all 128 s */
        int n  = tid;
        int ng = n0 + n;
        int h  = ng >> 6, d = ng & 63;
        int b  = m0 >> 9;
        int s  = m0 & 511;
        size_t R = ((size_t)b * HEADS + h) * DH + d;
        __half* dh = Oh + R * SEQ + s;
#pragma unroll
        for (int q = 0; q < 16; q++) {
            __align__(16) __half hv[8];
#pragma unroll
            for (int j = 0; j < 8; j++)
                hv[j] = __float2half_rn(stage[(q * 8 + j) * 133 + n]);
            *(uint4*)(dh + q * 8) = *(const uint4*)hv;
        }
    } else {
        int m = tid;
        float* dst = Of + (size_t)(m0 + m) * HID + n0;
        const float* bp = bias + n0;
#pragma unroll
        for (int q = 0; q < 32; q++) {
            __align__(16) float ov[4];
#pragma unroll
            for (int j = 0; j < 4; j++)
                ov[j] = stage[m * 133 + q * 4 + j] + bp[q * 4 + j];
            *(uint4*)(dst + q * 4) = *(const uint4*)ov;
        }
    }
}

/* ---------------------------- mix tensor GEMM ----------------------------- */
/* Out[b0+bb, t0+t, h*64+d] = relu( sum_s Mt[h,t,s] * X[b,s,h*64+d] + bias ),
   A = Mt (row-major t x s), B = Xt (row-major n x s). */
__global__ void __launch_bounds__(128, 2) gemm_mix_kernel(
    const __half* __restrict__ X, const __half* __restrict__ Mt,
    const float* __restrict__ bias, __half* __restrict__ Oh)
{
    extern __shared__ __align__(16) char smem[];
    uint32_t sb = smem_u32(smem);
    int tid = threadIdx.x, lane = tid & 31, wid = tid >> 5;
    int wm = wid & 1, wn = wid >> 1;
    int t0 = blockIdx.x * 128;
    int h  = blockIdx.y;
    int b0 = blockIdx.z * 2;

    const __half* Mh = Mt + (size_t)h * SEQ * SEQ;

    float acc[32][4];
#pragma unroll
    for (int i = 0; i < 32; i++)
#pragma unroll
        for (int j = 0; j < 4; j++) acc[i][j] = 0.f;

    const int NK = SEQ / KT;   /* 16 */
    stage_load_mix(sb,              Mh, X, t0, h, b0, 0);      cp_commit();
    stage_load_mix(sb + STAGEB,     Mh, X, t0, h, b0, KT);     cp_commit();
    stage_load_mix(sb + 2 * STAGEB, Mh, X, t0, h, b0, 2 * KT); cp_commit();

    for (int i = 0; i < NK; i++) {
        if (i + 1 < NK) cp_wait2(); else cp_wait0();
        __syncthreads();
        if (i + 3 < NK) {
            stage_load_mix(sb + ((i + 3) % NSTAGE) * STAGEB, Mh, X, t0, h, b0, (i + 3) * KT);
            cp_commit();
        }
        compute_ktile(sb + (i % NSTAGE) * STAGEB, acc, wm, wn, lane);
    }
    __syncthreads();

    float* stage = (float*)smem;
    acc_to_stage(stage, acc, wm, wn, lane);
    __syncthreads();

    /* bias + relu, write row-major fp16 hA; thread = one t, both bb */
    int m = tid;
#pragma unroll
    for (int half = 0; half < 2; half++) {
        size_t row = (size_t)(b0 + half) * SEQ + t0 + m;
        __half* dh = Oh + row * HID + h * DH;
        const float* bp = bias + h * DH;
#pragma unroll
        for (int q = 0; q < 8; q++) {
            __align__(16) __half hv[8];
#pragma unroll
            for (int j = 0; j < 8; j++) {
                float v = stage[m * 133 + half * 64 + q * 8 + j] + bp[q * 8 + j];
                hv[j] = __float2half_rn(fmaxf(v, 0.f));
            }
            *(uint4*)(dh + q * 8) = *(const uint4*)hv;
        }
    }
}

/* --------------------------- conversion kernels --------------------------- */
__global__ void __launch_bounds__(256) cvt_hi_kernel(
    const float* __restrict__ s, __half* __restrict__ dh, int n)
{
    for (int i = blockIdx.x * 256 + threadIdx.x; i < n; i += gridDim.x * 256)
        dh[i] = __float2half_rn(s[i]);
}

/* Mt[l,h,t,s] = M[l,h,s,t]; tiled 32x32 transpose + fp16 convert */
__global__ void __launch_bounds__(256) transpose_cvt_kernel(
    const float* __restrict__ M, __half* __restrict__ th)
{
    __shared__ float tile[32][33];
    const float* src = M + (size_t)blockIdx.z * SEQ * SEQ;
    int s0 = blockIdx.x * 32, t0 = blockIdx.y * 32;
    int tx = threadIdx.x, ty = threadIdx.y;
#pragma unroll
    for (int i = ty; i < 32; i += 8)
        tile[i][tx] = src[(size_t)(s0 + i) * SEQ + t0 + tx];
    __syncthreads();
    size_t ob = (size_t)blockIdx.z * SEQ * SEQ;
#pragma unroll
    for (int i = ty; i < 32; i += 8)
        th[ob + (size_t)(t0 + i) * SEQ + s0 + tx] = __float2half_rn(tile[tx][i]);
}

__global__ void __launch_bounds__(256) embed_ln_kernel(
    const int* __restrict__ x,
    const float* __restrict__ we, const float* __restrict__ pe,
    const float* __restrict__ te,
    const float* __restrict__ g, const float* __restrict__ beta,
    __half* __restrict__ oh)
{
    int row = blockIdx.x;
    int s   = row & (SEQ - 1);
    int tok = x[row];
    const float* w = we + (size_t)tok * HID;
    const float* p = pe + (size_t)s * HID;

    float v[3];
    float sum = 0.f;
#pragma unroll
    for (int i = 0; i < 3; i++) {
        int c = threadIdx.x + i * 256;
        v[i] = w[c] + p[c] + te[c];
        sum += v[i];
    }

    __shared__ float red[8];
    __shared__ float s_mu, s_rs;
#pragma unroll
    for (int o = 16; o > 0; o >>= 1) sum += __shfl_down_sync(0xffffffffu, sum, o);
    if ((threadIdx.x & 31) == 0) red[threadIdx.x >> 5] = sum;
    __syncthreads();
    if (threadIdx.x == 0) {
        float t = 0.f;
#pragma unroll
        for (int i = 0; i < 8; i++) t += red[i];
        s_mu = t * (1.f / HID);
    }
    __syncthreads();
    float mu = s_mu;

    float sq = 0.f;
#pragma unroll
    for (int i = 0; i < 3; i++) { float d = v[i] - mu; sq += d * d; }
#pragma unroll
    for (int o = 16; o > 0; o >>= 1) sq += __shfl_down_sync(0xffffffffu, sq, o);
    if ((threadIdx.x & 31) == 0) red[threadIdx.x >> 5] = sq;
    __syncthreads();
    if (threadIdx.x == 0) {
        float t = 0.f;
#pragma unroll
        for (int i = 0; i < 8; i++) t += red[i];
        s_rs = rsqrtf(t * (1.f / HID) + LN_EPS);
    }
    __syncthreads();
    float rs = s_rs;

#pragma unroll
    for (int i = 0; i < 3; i++) {
        int c = threadIdx.x + i * 256;
        float val = (v[i] - mu) * rs * g[c] + beta[c];
        oh[(size_t)row * HID + c] = __float2half_rn(val);
    }
}

/* --------------------------------- launch --------------------------------- */
extern "C" void kernel_launch(void* const* d_in, const int* in_sizes, int n_in,
                              void* d_out, int out_size)
{
    const int*   x   = (const int*)d_in[0];
    const float* we  = (const float*)d_in[1];
    const float* pe  = (const float*)d_in[2];
    const float* te  = (const float*)d_in[3];
    const float* lng = (const float*)d_in[4];
    const float* lnb = (const float*)d_in[5];
    const float* W   = (const float*)d_in[6];
    const float* bi  = (const float*)d_in[7];
    const float* Mm  = (const float*)d_in[8];
    const float* lw  = (const float*)d_in[9];
    const float* lb  = (const float*)d_in[10];
    float* out = (float*)d_out;

    __half *hA, *Xt, *Wh, *Mt;
    cudaGetSymbolAddress((void**)&hA, g_hA);
    cudaGetSymbolAddress((void**)&Xt, g_Xt);
    cudaGetSymbolAddress((void**)&Wh, g_W);
    cudaGetSymbolAddress((void**)&Mt, g_Mt);

    cudaFuncSetAttribute(gemm_dense_kernel<false>,
                         cudaFuncAttributeMaxDynamicSharedMemorySize, SMEM_DYN);
    cudaFuncSetAttribute(gemm_dense_kernel<true>,
                         cudaFuncAttributeMaxDynamicSharedMemorySize, SMEM_DYN);
    cudaFuncSetAttribute(gemm_mix_kernel,
                         cudaFuncAttributeMaxDynamicSharedMemorySize, SMEM_DYN);

    /* one-time conversions */
    embed_ln_kernel<<<ROWS, 256>>>(x, we, pe, te, lng, lnb, hA);
    cvt_hi_kernel<<<2048, 256>>>(W, Wh, LAYERS * HID * HID);
    cvt_hi_kernel<<<256, 256>>>(lw, Wh + (size_t)LAYERS * HID * HID, HID * HID);
    {
        dim3 tb(32, 8), tg(SEQ / 32, SEQ / 32, LAYERS * HEADS);
        transpose_cvt_kernel<<<tg, tb>>>(Mm, Mt);
    }

    dim3 gd(HID / 128, ROWS / 128);       /* (6, 128)    */
    dim3 gm(SEQ / 128, HEADS, BATCH / 2); /* (4, 12, 16) */
    for (int l = 0; l < LAYERS; l++) {
        gemm_dense_kernel<false><<<gd, 128, SMEM_DYN>>>(
            hA, Wh + (size_t)l * HID * HID, nullptr, Xt, nullptr);
        gemm_mix_kernel<<<gm, 128, SMEM_DYN>>>(
            Xt, Mt + (size_t)l * HEADS * SEQ * SEQ,
            bi + (size_t)l * HID, hA);
    }
    gemm_dense_kernel<true><<<gd, 128, SMEM_DYN>>>(
        hA, Wh + (size_t)LAYERS * HID * HID, lb, nullptr, out);
}

// round 7
// speedup vs baseline: 6.4788x; 1.0083x over previous
#include <cuda_runtime.h>
#include <cuda_fp16.h>
#include <stdint.h>

#define SEQ    512
#define HID    768
#define HEADS  12
#define DH     64
#define LAYERS 12
#define BATCH  32
#define ROWS   (BATCH * SEQ)   /* 16384 */
#define LN_EPS 1e-12f

#define KT   64                 /* fp16 k per stage            */
#define RSE  72                 /* smem row stride, elements   */
#define RSB  144                /* smem row stride, bytes      */
#define BUFB (128 * RSB)        /* one operand buffer: 18432 B */
#define STAGEB (2 * BUFB)       /* A, B: 36864 B               */
#define NSTAGE 3
#define OFF_A 0
#define OFF_B BUFB
#define SMEM_DYN (NSTAGE * STAGEB)   /* 110592 B (>= 128*133*4 epilogue) */

/* ------------------------- device scratch (static) ------------------------ */
__device__ __half g_hA[(size_t)ROWS * HID];
__device__ __half g_Xt[(size_t)ROWS * HID];   /* [B*HEADS*DH][SEQ] */
__device__ __half g_W[(size_t)(LAYERS + 1) * HID * HID];
__device__ __half g_Mt[(size_t)LAYERS * HEADS * SEQ * SEQ];

/* ------------------------------ PTX helpers ------------------------------ */
__device__ __forceinline__ uint32_t smem_u32(const void* p) {
    uint32_t a;
    asm("{ .reg .u64 t; cvta.to.shared.u64 t, %1; cvt.u32.u64 %0, t; }"
        : "=r"(a) : "l"(p));
    return a;
}
__device__ __forceinline__ void cpa16(uint32_t dst, const void* src) {
    asm volatile("cp.async.cg.shared.global [%0], [%1], 16;"
                 :: "r"(dst), "l"(src) : "memory");
}
__device__ __forceinline__ void cp_commit() {
    asm volatile("cp.async.commit_group;" ::: "memory");
}
__device__ __forceinline__ void cp_wait1() {
    asm volatile("cp.async.wait_group 1;" ::: "memory");
}
__device__ __forceinline__ void cp_wait0() {
    asm volatile("cp.async.wait_group 0;" ::: "memory");
}
__device__ __forceinline__ void ldm_x4(uint32_t* r, uint32_t addr) {
    asm volatile("ldmatrix.sync.aligned.m8n8.x4.shared.b16 {%0,%1,%2,%3}, [%4];"
                 : "=r"(r[0]), "=r"(r[1]), "=r"(r[2]), "=r"(r[3]) : "r"(addr));
}
__device__ __forceinline__ void mma16816(float* c, const uint32_t* a, const uint32_t* b) {
    asm volatile(
        "mma.sync.aligned.m16n8k16.row.col.f32.f16.f16.f32 "
        "{%0,%1,%2,%3},{%4,%5,%6,%7},{%8,%9},{%0,%1,%2,%3};"
        : "+f"(c[0]), "+f"(c[1]), "+f"(c[2]), "+f"(c[3])
        : "r"(a[0]), "r"(a[1]), "r"(a[2]), "r"(a[3]), "r"(b[0]), "r"(b[1]));
}

/* ------------------------------ stage loaders ----------------------------- */
/* 2 buffers x 1024 16B chunks; 16 per thread (128 threads). buf = i>>3. */
__device__ __forceinline__ void stage_load_dense(
    uint32_t sm, const __half* A, const __half* W, int m0, int n0, int k0)
{
    int tid = threadIdx.x;
#pragma unroll
    for (int i = 0; i < 16; i++) {
        const int buf = i >> 3;
        int rem = tid + (i & 7) * 128;
        int row = rem >> 3;
        int c   = rem & 7;
        const __half* src = buf
            ? W + (size_t)(n0 + row) * HID + k0 + c * 8
            : A + (size_t)(m0 + row) * HID + k0 + c * 8;
        cpa16(sm + buf * BUFB + row * RSB + c * 16, src);
    }
}
__device__ __forceinline__ void stage_load_mix(
    uint32_t sm, const __half* M, const __half* X,
    int t0, int h, int b0, int s0)
{
    int tid = threadIdx.x;
#pragma unroll
    for (int i = 0; i < 16; i++) {
        const int buf = i >> 3;
        int rem = tid + (i & 7) * 128;
        int row = rem >> 3;
        int c   = rem & 7;
        const __half* src;
        if (buf == 0) {
            src = M + (size_t)(t0 + row) * SEQ + s0 + c * 8;
        } else {
            int bb = row >> 6, d = row & 63;
            size_t R = ((size_t)(b0 + bb) * HEADS + h) * DH + d;
            src = X + R * SEQ + s0 + c * 8;
        }
        cpa16(sm + buf * BUFB + row * RSB + c * 16, src);
    }
}

/* ------------------------------- MMA core -------------------------------- */
/* 4 warps, each computes a 64m x 64n tile; acc[32][4]. KT=64: 4 sub-k steps. */
__device__ __forceinline__ void compute_ktile(
    uint32_t sbase, float (*acc)[4], int wm, int wn, int lane)
{
    const int ar = lane & 15;
    const int ac = (lane >> 4) * 8;
    const int br = ((lane >> 4) << 3) + (lane & 7);
    const int bc = ((lane >> 3) & 1) * 8;
#pragma unroll
    for (int ks = 0; ks < 4; ks++) {
        uint32_t af[16];
#pragma unroll
        for (int mi = 0; mi < 4; mi++) {
            uint32_t off = ((wm * 64 + mi * 16 + ar) * RSE + ks * 16 + ac) * 2;
            ldm_x4(af + 4 * mi, sbase + OFF_A + off);
        }
#pragma unroll
        for (int nh = 0; nh < 2; nh++) {
            uint32_t bf[8];
#pragma unroll
            for (int g = 0; g < 2; g++) {
                uint32_t off = ((wn * 64 + nh * 32 + g * 16 + br) * RSE + ks * 16 + bc) * 2;
                ldm_x4(bf + 4 * g, sbase + OFF_B + off);
            }
#pragma unroll
            for (int mi = 0; mi < 4; mi++)
#pragma unroll
                for (int nj = 0; nj < 4; nj++)
                    mma16816(acc[mi * 8 + nh * 4 + nj], af + 4 * mi, bf + 2 * nj);
        }
    }
}

/* dump acc tile into padded f32 smem stage [128][133] */
__device__ __forceinline__ void acc_to_stage(
    float* stage, float (*acc)[4], int wm, int wn, int lane)
{
#pragma unroll
    for (int mi = 0; mi < 4; mi++)
#pragma unroll
        for (int nj = 0; nj < 8; nj++) {
            int r  = wm * 64 + mi * 16 + (lane >> 2);
            int cn = wn * 64 + nj * 8 + (lane & 3) * 2;
            float* p = stage + r * 133 + cn;
            p[0] = acc[mi * 8 + nj][0];
            p[1] = acc[mi * 8 + nj][1];
            p += 8 * 133;
            p[0] = acc[mi * 8 + nj][2];
            p[1] = acc[mi * 8 + nj][3];
        }
}

/* --------------------------- dense tensor GEMM ---------------------------- */
/* D[m,n] = sum_k A[m,k]*W[n,k].
   FINAL=false: write fp16 TRANSPOSED into Xt[(b*HEADS+h)*DH+d][s].
   FINAL=true : write f32 + bias row-major to Of. */
template <bool FINAL>
__global__ void __launch_bounds__(128, 2) gemm_dense_kernel(
    const __half* __restrict__ A, const __half* __restrict__ W,
    const float* __restrict__ bias,
    __half* __restrict__ Oh, float* __restrict__ Of)
{
    extern __shared__ __align__(16) char smem[];
    uint32_t sb = smem_u32(smem);
    int tid = threadIdx.x, lane = tid & 31, wid = tid >> 5;
    int wm = wid & 1, wn = wid >> 1;
    int n0 = blockIdx.x * 128, m0 = blockIdx.y * 128;

    float acc[32][4];
#pragma unroll
    for (int i = 0; i < 32; i++)
#pragma unroll
        for (int j = 0; j < 4; j++) acc[i][j] = 0.f;

    const int NK = HID / KT;   /* 12 */
    stage_load_dense(sb,          A, W, m0, n0, 0);  cp_commit();
    stage_load_dense(sb + STAGEB, A, W, m0, n0, KT); cp_commit();

    for (int i = 0; i < NK; i++) {
        if (i + 1 < NK) cp_wait1(); else cp_wait0();
        __syncthreads();
        if (i + 2 < NK) {
            stage_load_dense(sb + ((i + 2) % NSTAGE) * STAGEB, A, W, m0, n0, (i + 2) * KT);
            cp_commit();
        }
        compute_ktile(sb + (i % NSTAGE) * STAGEB, acc, wm, wn, lane);
    }
    __syncthreads();

    float* stage = (float*)smem;
    acc_to_stage(stage, acc, wm, wn, lane);
    __syncthreads();

    if (!FINAL) {
        /* transposed fp16 write: thread -> one n-row, all 128 s */
        int n  = tid;
        int ng = n0 + n;
        int h  = ng >> 6, d = ng & 63;
        int b  = m0 >> 9;
        int s  = m0 & 511;
        size_t R = ((size_t)b * HEADS + h) * DH + d;
        __half* dh = Oh + R * SEQ + s;
#pragma unroll
        for (int q = 0; q < 16; q++) {
            __align__(16) __half hv[8];
#pragma unroll
            for (int j = 0; j < 8; j++)
                hv[j] = __float2half_rn(stage[(q * 8 + j) * 133 + n]);
            *(uint4*)(dh + q * 8) = *(const uint4*)hv;
        }
    } else {
        int m = tid;
        float* dst = Of + (size_t)(m0 + m) * HID + n0;
        const float* bp = bias + n0;
#pragma unroll
        for (int q = 0; q < 32; q++) {
            __align__(16) float ov[4];
#pragma unroll
            for (int j = 0; j < 4; j++)
                ov[j] = stage[m * 133 + q * 4 + j] + bp[q * 4 + j];
            *(uint4*)(dst + q * 4) = *(const uint4*)ov;
        }
    }
}

/* ---------------------------- mix tensor GEMM ----------------------------- */
/* Out[b0+bb, t0+t, h*64+d] = relu( sum_s Mt[h,t,s] * X[b,s,h*64+d] + bias ),
   A = Mt (row-major t x s), B = Xt (row-major n x s). */
__global__ void __launch_bounds__(128, 2) gemm_mix_kernel(
    const __half* __restrict__ X, const __half* __restrict__ Mt,
    const float* __restrict__ bias, __half* __restrict__ Oh)
{
    extern __shared__ __align__(16) char smem[];
    uint32_t sb = smem_u32(smem);
    int tid = threadIdx.x, lane = tid & 31, wid = tid >> 5;
    int wm = wid & 1, wn = wid >> 1;
    int t0 = blockIdx.x * 128;
    int h  = blockIdx.y;
    int b0 = blockIdx.z * 2;

    const __half* Mh = Mt + (size_t)h * SEQ * SEQ;

    float acc[32][4];
#pragma unroll
    for (int i = 0; i < 32; i++)
#pragma unroll
        for (int j = 0; j < 4; j++) acc[i][j] = 0.f;

    const int NK = SEQ / KT;   /* 8 */
    stage_load_mix(sb,          Mh, X, t0, h, b0, 0);  cp_commit();
    stage_load_mix(sb + STAGEB, Mh, X, t0, h, b0, KT); cp_commit();

    for (int i = 0; i < NK; i++) {
        if (i + 1 < NK) cp_wait1(); else cp_wait0();
        __syncthreads();
        if (i + 2 < NK) {
            stage_load_mix(sb + ((i + 2) % NSTAGE) * STAGEB, Mh, X, t0, h, b0, (i + 2) * KT);
            cp_commit();
        }
        compute_ktile(sb + (i % NSTAGE) * STAGEB, acc, wm, wn, lane);
    }
    __syncthreads();

    float* stage = (float*)smem;
    acc_to_stage(stage, acc, wm, wn, lane);
    __syncthreads();

    /* bias + relu, write row-major fp16 hA; thread = one t, both bb */
    int m = tid;
#pragma unroll
    for (int half = 0; half < 2; half++) {
        size_t row = (size_t)(b0 + half) * SEQ + t0 + m;
        __half* dh = Oh + row * HID + h * DH;
        const float* bp = bias + h * DH;
#pragma unroll
        for (int q = 0; q < 8; q++) {
            __align__(16) __half hv[8];
#pragma unroll
            for (int j = 0; j < 8; j++) {
                float v = stage[m * 133 + half * 64 + q * 8 + j] + bp[q * 8 + j];
                hv[j] = __float2half_rn(fmaxf(v, 0.f));
            }
            *(uint4*)(dh + q * 8) = *(const uint4*)hv;
        }
    }
}

/* --------------------------- conversion kernels --------------------------- */
/* vectorized f32 -> f16: 4 elements per thread iteration */
__global__ void __launch_bounds__(256) cvt_hi_kernel(
    const float* __restrict__ s, __half* __restrict__ dh, int n4)
{
    for (int i = blockIdx.x * 256 + threadIdx.x; i < n4; i += gridDim.x * 256) {
        float4 v = ((const float4*)s)[i];
        __align__(8) __half o[4];
        o[0] = __float2half_rn(v.x); o[1] = __float2half_rn(v.y);
        o[2] = __float2half_rn(v.z); o[3] = __float2half_rn(v.w);
        ((uint2*)dh)[i] = *(const uint2*)o;
    }
}

/* Mt[l,h,t,s] = M[l,h,s,t]; 32x32 transpose, 4 matrices per block (z-batch). */
__global__ void __launch_bounds__(256) transpose_cvt_kernel(
    const float* __restrict__ M, __half* __restrict__ th)
{
    __shared__ float tile[32][33];
    int s0 = blockIdx.x * 32, t0 = blockIdx.y * 32;
    int tx = threadIdx.x, ty = threadIdx.y;
#pragma unroll 1
    for (int zz = 0; zz < 4; zz++) {
        int z = blockIdx.z * 4 + zz;
        const float* src = M + (size_t)z * SEQ * SEQ;
        size_t ob = (size_t)z * SEQ * SEQ;
#pragma unroll
        for (int i = ty; i < 32; i += 8)
            tile[i][tx] = src[(size_t)(s0 + i) * SEQ + t0 + tx];
        __syncthreads();
#pragma unroll
        for (int i = ty; i < 32; i += 8)
            th[ob + (size_t)(t0 + i) * SEQ + s0 + tx] = __float2half_rn(tile[tx][i]);
        __syncthreads();
    }
}

__global__ void __launch_bounds__(256) embed_ln_kernel(
    const int* __restrict__ x,
    const float* __restrict__ we, const float* __restrict__ pe,
    const float* __restrict__ te,
    const float* __restrict__ g, const float* __restrict__ beta,
    __half* __restrict__ oh)
{
    int row = blockIdx.x;
    int s   = row & (SEQ - 1);
    int tok = x[row];
    const float* w = we + (size_t)tok * HID;
    const float* p = pe + (size_t)s * HID;

    float v[3];
    float sum = 0.f;
#pragma unroll
    for (int i = 0; i < 3; i++) {
        int c = threadIdx.x + i * 256;
        v[i] = w[c] + p[c] + te[c];
        sum += v[i];
    }

    __shared__ float red[8];
    __shared__ float s_mu, s_rs;
#pragma unroll
    for (int o = 16; o > 0; o >>= 1) sum += __shfl_down_sync(0xffffffffu, sum, o);
    if ((threadIdx.x & 31) == 0) red[threadIdx.x >> 5] = sum;
    __syncthreads();
    if (threadIdx.x == 0) {
        float t = 0.f;
#pragma unroll
        for (int i = 0; i < 8; i++) t += red[i];
        s_mu = t * (1.f / HID);
    }
    __syncthreads();
    float mu = s_mu;

    float sq = 0.f;
#pragma unroll
    for (int i = 0; i < 3; i++) { float d = v[i] - mu; sq += d * d; }
#pragma unroll
    for (int o = 16; o > 0; o >>= 1) sq += __shfl_down_sync(0xffffffffu, sq, o);
    if ((threadIdx.x & 31) == 0) red[threadIdx.x >> 5] = sq;
    __syncthreads();
    if (threadIdx.x == 0) {
        float t = 0.f;
#pragma unroll
        for (int i = 0; i < 8; i++) t += red[i];
        s_rs = rsqrtf(t * (1.f / HID) + LN_EPS);
    }
    __syncthreads();
    float rs = s_rs;

#pragma unroll
    for (int i = 0; i < 3; i++) {
        int c = threadIdx.x + i * 256;
        float val = (v[i] - mu) * rs * g[c] + beta[c];
        oh[(size_t)row * HID + c] = __float2half_rn(val);
    }
}

/* --------------------------------- launch --------------------------------- */
extern "C" void kernel_launch(void* const* d_in, const int* in_sizes, int n_in,
                              void* d_out, int out_size)
{
    const int*   x   = (const int*)d_in[0];
    const float* we  = (const float*)d_in[1];
    const float* pe  = (const float*)d_in[2];
    const float* te  = (const float*)d_in[3];
    const float* lng = (const float*)d_in[4];
    const float* lnb = (const float*)d_in[5];
    const float* W   = (const float*)d_in[6];
    const float* bi  = (const float*)d_in[7];
    const float* Mm  = (const float*)d_in[8];
    const float* lw  = (const float*)d_in[9];
    const float* lb  = (const float*)d_in[10];
    float* out = (float*)d_out;

    __half *hA, *Xt, *Wh, *Mt;
    cudaGetSymbolAddress((void**)&hA, g_hA);
    cudaGetSymbolAddress((void**)&Xt, g_Xt);
    cudaGetSymbolAddress((void**)&Wh, g_W);
    cudaGetSymbolAddress((void**)&Mt, g_Mt);

    cudaFuncSetAttribute(gemm_dense_kernel<false>,
                         cudaFuncAttributeMaxDynamicSharedMemorySize, SMEM_DYN);
    cudaFuncSetAttribute(gemm_dense_kernel<true>,
                         cudaFuncAttributeMaxDynamicSharedMemorySize, SMEM_DYN);
    cudaFuncSetAttribute(gemm_mix_kernel,
                         cudaFuncAttributeMaxDynamicSharedMemorySize, SMEM_DYN);

    /* one-time conversions */
    embed_ln_kernel<<<ROWS, 256>>>(x, we, pe, te, lng, lnb, hA);
    cvt_hi_kernel<<<1024, 256>>>(W, Wh, LAYERS * HID * HID / 4);
    cvt_hi_kernel<<<144, 256>>>(lw, Wh + (size_t)LAYERS * HID * HID, HID * HID / 4);
    {
        dim3 tb(32, 8), tg(SEQ / 32, SEQ / 32, LAYERS * HEADS / 4);
        transpose_cvt_kernel<<<tg, tb>>>(Mm, Mt);
    }

    dim3 gd(HID / 128, ROWS / 128);       /* (6, 128)    */
    dim3 gm(SEQ / 128, HEADS, BATCH / 2); /* (4, 12, 16) */
    for (int l = 0; l < LAYERS; l++) {
        gemm_dense_kernel<false><<<gd, 128, SMEM_DYN>>>(
            hA, Wh + (size_t)l * HID * HID, nullptr, Xt, nullptr);
        gemm_mix_kernel<<<gm, 128, SMEM_DYN>>>(
            Xt, Mt + (size_t)l * HEADS * SEQ * SEQ,
            bi + (size_t)l * HID, hA);
    }
    gemm_dense_kernel<true><<<gd, 128, SMEM_DYN>>>(
        hA, Wh + (size_t)LAYERS * HID * HID, lb, nullptr, out);
}

// round 8
// speedup vs baseline: 6.5883x; 1.0169x over previous
#include <cuda_runtime.h>
#include <cuda_fp16.h>
#include <stdint.h>

#define SEQ    512
#define HID    768
#define HEADS  12
#define DH     64
#define LAYERS 12
#define BATCH  32
#define ROWS   (BATCH * SEQ)   /* 16384 */
#define LN_EPS 1e-12f

#define KT   32                 /* fp16 k per stage            */
#define RSE  40                 /* smem row stride, elements   */
#define RSB  80                 /* smem row stride, bytes      */
#define BUFB (128 * RSB)        /* one operand buffer: 10240 B */
#define STAGEB (2 * BUFB)       /* A, B: 20480 B               */
#define NSTAGE 3
#define OFF_A 0
#define OFF_B BUFB
#define SMEM_DYN (NSTAGE * STAGEB)   /* 61440 B (>= 128*136*2 fp16 stage) */

/* ------------------------- device scratch (static) ------------------------ */
__device__ __half g_hA[(size_t)ROWS * HID];
__device__ __half g_Xt[(size_t)ROWS * HID];   /* [B*HEADS*DH][SEQ] */
__device__ __half g_W[(size_t)(LAYERS + 1) * HID * HID];
__device__ __half g_Mt[(size_t)LAYERS * HEADS * SEQ * SEQ];

/* ------------------------------ PTX helpers ------------------------------ */
__device__ __forceinline__ uint32_t smem_u32(const void* p) {
    uint32_t a;
    asm("{ .reg .u64 t; cvta.to.shared.u64 t, %1; cvt.u32.u64 %0, t; }"
        : "=r"(a) : "l"(p));
    return a;
}
__device__ __forceinline__ void cpa16(uint32_t dst, const void* src) {
    asm volatile("cp.async.cg.shared.global [%0], [%1], 16;"
                 :: "r"(dst), "l"(src) : "memory");
}
__device__ __forceinline__ void cp_commit() {
    asm volatile("cp.async.commit_group;" ::: "memory");
}
__device__ __forceinline__ void cp_wait1() {
    asm volatile("cp.async.wait_group 1;" ::: "memory");
}
__device__ __forceinline__ void cp_wait0() {
    asm volatile("cp.async.wait_group 0;" ::: "memory");
}
__device__ __forceinline__ void ldm_x4(uint32_t* r, uint32_t addr) {
    asm volatile("ldmatrix.sync.aligned.m8n8.x4.shared.b16 {%0,%1,%2,%3}, [%4];"
                 : "=r"(r[0]), "=r"(r[1]), "=r"(r[2]), "=r"(r[3]) : "r"(addr));
}
__device__ __forceinline__ void mma16816(float* c, const uint32_t* a, const uint32_t* b) {
    asm volatile(
        "mma.sync.aligned.m16n8k16.row.col.f32.f16.f16.f32 "
        "{%0,%1,%2,%3},{%4,%5,%6,%7},{%8,%9},{%0,%1,%2,%3};"
        : "+f"(c[0]), "+f"(c[1]), "+f"(c[2]), "+f"(c[3])
        : "r"(a[0]), "r"(a[1]), "r"(a[2]), "r"(a[3]), "r"(b[0]), "r"(b[1]));
}

/* ------------------------------ stage loaders ----------------------------- */
/* 2 buffers x 512 16B chunks; 8 per thread (128 threads). buf = i>>2. */
__device__ __forceinline__ void stage_load_dense(
    uint32_t sm, const __half* A, const __half* W, int m0, int n0, int k0)
{
    int tid = threadIdx.x;
#pragma unroll
    for (int i = 0; i < 8; i++) {
        const int buf = i >> 2;
        int rem = tid + (i & 3) * 128;
        int row = rem >> 2;
        int c   = rem & 3;
        const __half* src = buf
            ? W + (size_t)(n0 + row) * HID + k0 + c * 8
            : A + (size_t)(m0 + row) * HID + k0 + c * 8;
        cpa16(sm + buf * BUFB + row * RSB + c * 16, src);
    }
}
__device__ __forceinline__ void stage_load_mix(
    uint32_t sm, const __half* M, const __half* X,
    int t0, int h, int b0, int s0)
{
    int tid = threadIdx.x;
#pragma unroll
    for (int i = 0; i < 8; i++) {
        const int buf = i >> 2;
        int rem = tid + (i & 3) * 128;
        int row = rem >> 2;
        int c   = rem & 3;
        const __half* src;
        if (buf == 0) {
            src = M + (size_t)(t0 + row) * SEQ + s0 + c * 8;
        } else {
            int bb = row >> 6, d = row & 63;
            size_t R = ((size_t)(b0 + bb) * HEADS + h) * DH + d;
            src = X + R * SEQ + s0 + c * 8;
        }
        cpa16(sm + buf * BUFB + row * RSB + c * 16, src);
    }
}

/* ------------------------------- MMA core -------------------------------- */
/* 4 warps, each computes a 64m x 64n tile; acc[32][4]. KT=32: 2 sub-k steps. */
__device__ __forceinline__ void compute_ktile(
    uint32_t sbase, float (*acc)[4], int wm, int wn, int lane)
{
    const int ar = lane & 15;
    const int ac = (lane >> 4) * 8;
    const int br = ((lane >> 4) << 3) + (lane & 7);
    const int bc = ((lane >> 3) & 1) * 8;
#pragma unroll
    for (int ks = 0; ks < 2; ks++) {
        uint32_t af[16];
#pragma unroll
        for (int mi = 0; mi < 4; mi++) {
            uint32_t off = ((wm * 64 + mi * 16 + ar) * RSE + ks * 16 + ac) * 2;
            ldm_x4(af + 4 * mi, sbase + OFF_A + off);
        }
#pragma unroll
        for (int nh = 0; nh < 2; nh++) {
            uint32_t bf[8];
#pragma unroll
            for (int g = 0; g < 2; g++) {
                uint32_t off = ((wn * 64 + nh * 32 + g * 16 + br) * RSE + ks * 16 + bc) * 2;
                ldm_x4(bf + 4 * g, sbase + OFF_B + off);
            }
#pragma unroll
            for (int mi = 0; mi < 4; mi++)
#pragma unroll
                for (int nj = 0; nj < 4; nj++)
                    mma16816(acc[mi * 8 + nh * 4 + nj], af + 4 * mi, bf + 2 * nj);
        }
    }
}

/* --------------------------- dense tensor GEMM ---------------------------- */
/* D[m,n] = sum_k A[m,k]*W[n,k].
   FINAL=false: write fp16 TRANSPOSED into Xt[(b*HEADS+h)*DH+d][s] via fp16 stage.
   FINAL=true : direct reg->global f32 + bias, no staging. */
template <bool FINAL>
__global__ void __launch_bounds__(128, 3) gemm_dense_kernel(
    const __half* __restrict__ A, const __half* __restrict__ W,
    const float* __restrict__ bias,
    __half* __restrict__ Oh, float* __restrict__ Of)
{
    extern __shared__ __align__(16) char smem[];
    uint32_t sb = smem_u32(smem);
    int tid = threadIdx.x, lane = tid & 31, wid = tid >> 5;
    int wm = wid & 1, wn = wid >> 1;
    int n0 = blockIdx.x * 128, m0 = blockIdx.y * 128;

    float acc[32][4];
#pragma unroll
    for (int i = 0; i < 32; i++)
#pragma unroll
        for (int j = 0; j < 4; j++) acc[i][j] = 0.f;

    const int NK = HID / KT;   /* 24 */
    stage_load_dense(sb,          A, W, m0, n0, 0);  cp_commit();
    stage_load_dense(sb + STAGEB, A, W, m0, n0, KT); cp_commit();

    for (int i = 0; i < NK; i++) {
        if (i + 1 < NK) cp_wait1(); else cp_wait0();
        __syncthreads();
        if (i + 2 < NK) {
            stage_load_dense(sb + ((i + 2) % NSTAGE) * STAGEB, A, W, m0, n0, (i + 2) * KT);
            cp_commit();
        }
        compute_ktile(sb + (i % NSTAGE) * STAGEB, acc, wm, wn, lane);
    }

    if (FINAL) {
        /* direct reg -> global f32 + bias (no staging) */
        const int r0 = wm * 64 + (lane >> 2);
        const int c0 = wn * 64 + (lane & 3) * 2;
#pragma unroll
        for (int mi = 0; mi < 4; mi++)
#pragma unroll
            for (int njj = 0; njj < 8; njj++) {
                int m = m0 + r0 + mi * 16;
                int n = n0 + c0 + (njj >> 2) * 32 + (njj & 3) * 8;
                const float* ac = acc[mi * 8 + njj];
                float b0v = bias[n], b1v = bias[n + 1];
                float2 v0 = make_float2(ac[0] + b0v, ac[1] + b1v);
                float2 v1 = make_float2(ac[2] + b0v, ac[3] + b1v);
                *(float2*)&Of[(size_t)m * HID + n]       = v0;
                *(float2*)&Of[(size_t)(m + 8) * HID + n] = v1;
            }
        return;
    }

    /* transposed fp16 write via fp16 stage [128][136] */
    __syncthreads();
    __half* hst = (__half*)smem;
#pragma unroll
    for (int mi = 0; mi < 4; mi++)
#pragma unroll
        for (int njj = 0; njj < 8; njj++) {
            int r  = wm * 64 + mi * 16 + (lane >> 2);
            int cn = wn * 64 + (njj >> 2) * 32 + (njj & 3) * 8 + (lane & 3) * 2;
            const float* ac = acc[mi * 8 + njj];
            *(half2*)&hst[r * 136 + cn]       = __floats2half2_rn(ac[0], ac[1]);
            *(half2*)&hst[(r + 8) * 136 + cn] = __floats2half2_rn(ac[2], ac[3]);
        }
    __syncthreads();

    int n  = tid;
    int ng = n0 + n;
    int h  = ng >> 6, d = ng & 63;
    int b  = m0 >> 9;
    int s  = m0 & 511;
    size_t R = ((size_t)b * HEADS + h) * DH + d;
    __half* dh = Oh + R * SEQ + s;
#pragma unroll
    for (int q = 0; q < 16; q++) {
        __align__(16) __half hv[8];
#pragma unroll
        for (int j = 0; j < 8; j++)
            hv[j] = hst[(q * 8 + j) * 136 + n];
        *(uint4*)(dh + q * 8) = *(const uint4*)hv;
    }
}

/* ---------------------------- mix tensor GEMM ----------------------------- */
/* Out[b0+bb, t0+t, h*64+d] = relu( sum_s Mt[h,t,s] * X[b,s,h*64+d] + bias ),
   A = Mt (row-major t x s), B = Xt (row-major n x s).  Direct reg epilogue. */
__global__ void __launch_bounds__(128, 3) gemm_mix_kernel(
    const __half* __restrict__ X, const __half* __restrict__ Mt,
    const float* __restrict__ bias, __half* __restrict__ Oh)
{
    extern __shared__ __align__(16) char smem[];
    uint32_t sb = smem_u32(smem);
    int tid = threadIdx.x, lane = tid & 31, wid = tid >> 5;
    int wm = wid & 1, wn = wid >> 1;
    int t0 = blockIdx.x * 128;
    int h  = blockIdx.y;
    int b0 = blockIdx.z * 2;

    const __half* Mh = Mt + (size_t)h * SEQ * SEQ;

    float acc[32][4];
#pragma unroll
    for (int i = 0; i < 32; i++)
#pragma unroll
        for (int j = 0; j < 4; j++) acc[i][j] = 0.f;

    const int NK = SEQ / KT;   /* 16 */
    stage_load_mix(sb,          Mh, X, t0, h, b0, 0);  cp_commit();
    stage_load_mix(sb + STAGEB, Mh, X, t0, h, b0, KT); cp_commit();

    for (int i = 0; i < NK; i++) {
        if (i + 1 < NK) cp_wait1(); else cp_wait0();
        __syncthreads();
        if (i + 2 < NK) {
            stage_load_mix(sb + ((i + 2) % NSTAGE) * STAGEB, Mh, X, t0, h, b0, (i + 2) * KT);
            cp_commit();
        }
        compute_ktile(sb + (i % NSTAGE) * STAGEB, acc, wm, wn, lane);
    }

    /* direct reg -> global: bias + relu + cvt, half2 stores */
    const int r0 = wm * 64 + (lane >> 2);
    const int c0 = wn * 64 + (lane & 3) * 2;
#pragma unroll
    for (int mi = 0; mi < 4; mi++)
#pragma unroll
        for (int njj = 0; njj < 8; njj++) {
            int m = t0 + r0 + mi * 16;
            int n = c0 + (njj >> 2) * 32 + (njj & 3) * 8;   /* 0..127 */
            int bb = n >> 6, d = n & 63;
            int col = h * DH + d;
            const float* ac = acc[mi * 8 + njj];
            float b0v = bias[col], b1v = bias[col + 1];
            size_t rowg = (size_t)(b0 + bb) * SEQ + m;
            half2 v0 = __floats2half2_rn(fmaxf(ac[0] + b0v, 0.f), fmaxf(ac[1] + b1v, 0.f));
            half2 v1 = __floats2half2_rn(fmaxf(ac[2] + b0v, 0.f), fmaxf(ac[3] + b1v, 0.f));
            *(half2*)&Oh[rowg * HID + col]                 = v0;
            *(half2*)&Oh[(rowg + 8) * HID + col]           = v1;
        }
}

/* --------------------------- conversion kernels --------------------------- */
/* vectorized f32 -> f16: 4 elements per thread iteration */
__global__ void __launch_bounds__(256) cvt_hi_kernel(
    const float* __restrict__ s, __half* __restrict__ dh, int n4)
{
    for (int i = blockIdx.x * 256 + threadIdx.x; i < n4; i += gridDim.x * 256) {
        float4 v = ((const float4*)s)[i];
        __align__(8) __half o[4];
        o[0] = __float2half_rn(v.x); o[1] = __float2half_rn(v.y);
        o[2] = __float2half_rn(v.z); o[3] = __float2half_rn(v.w);
        ((uint2*)dh)[i] = *(const uint2*)o;
    }
}

/* Mt[l,h,t,s] = M[l,h,s,t]; 32x32 transpose, vectorized 8B stores, z-batch 4. */
__global__ void __launch_bounds__(256) transpose_cvt_kernel(
    const float* __restrict__ M, __half* __restrict__ th)
{
    __shared__ float tile[32][33];
    int s0 = blockIdx.x * 32, t0 = blockIdx.y * 32;
    int tx = threadIdx.x & 31, ty = threadIdx.x >> 5;   /* (32,8) */
    int wt = threadIdx.x >> 3;          /* t index 0..31 */
    int sq = (threadIdx.x & 7) * 4;     /* s quad base   */
#pragma unroll 1
    for (int zz = 0; zz < 4; zz++) {
        int z = blockIdx.z * 4 + zz;
        const float* src = M + (size_t)z * SEQ * SEQ;
        size_t ob = (size_t)z * SEQ * SEQ;
#pragma unroll
        for (int i = ty; i < 32; i += 8)
            tile[i][tx] = src[(size_t)(s0 + i) * SEQ + t0 + tx];
        __syncthreads();
        __align__(8) __half o[4];
#pragma unroll
        for (int j = 0; j < 4; j++)
            o[j] = __float2half_rn(tile[sq + j][wt]);
        *(uint2*)&th[ob + (size_t)(t0 + wt) * SEQ + s0 + sq] = *(const uint2*)o;
        __syncthreads();
    }
}

__global__ void __launch_bounds__(256) embed_ln_kernel(
    const int* __restrict__ x,
    const float* __restrict__ we, const float* __restrict__ pe,
    const float* __restrict__ te,
    const float* __restrict__ g, const float* __restrict__ beta,
    __half* __restrict__ oh)
{
    int row = blockIdx.x;
    int s   = row & (SEQ - 1);
    int tok = x[row];
    const float* w = we + (size_t)tok * HID;
    const float* p = pe + (size_t)s * HID;

    float v[3];
    float sum = 0.f;
#pragma unroll
    for (int i = 0; i < 3; i++) {
        int c = threadIdx.x + i * 256;
        v[i] = w[c] + p[c] + te[c];
        sum += v[i];
    }

    __shared__ float red[8];
    __shared__ float s_mu, s_rs;
#pragma unroll
    for (int o = 16; o > 0; o >>= 1) sum += __shfl_down_sync(0xffffffffu, sum, o);
    if ((threadIdx.x & 31) == 0) red[threadIdx.x >> 5] = sum;
    __syncthreads();
    if (threadIdx.x == 0) {
        float t = 0.f;
#pragma unroll
        for (int i = 0; i < 8; i++) t += red[i];
        s_mu = t * (1.f / HID);
    }
    __syncthreads();
    float mu = s_mu;

    float sq = 0.f;
#pragma unroll
    for (int i = 0; i < 3; i++) { float d = v[i] - mu; sq += d * d; }
#pragma unroll
    for (int o = 16; o > 0; o >>= 1) sq += __shfl_down_sync(0xffffffffu, sq, o);
    if ((threadIdx.x & 31) == 0) red[threadIdx.x >> 5] = sq;
    __syncthreads();
    if (threadIdx.x == 0) {
        float t = 0.f;
#pragma unroll
        for (int i = 0; i < 8; i++) t += red[i];
        s_rs = rsqrtf(t * (1.f / HID) + LN_EPS);
    }
    __syncthreads();
    float rs = s_rs;

#pragma unroll
    for (int i = 0; i < 3; i++) {
        int c = threadIdx.x + i * 256;
        float val = (v[i] - mu) * rs * g[c] + beta[c];
        oh[(size_t)row * HID + c] = __float2half_rn(val);
    }
}

/* --------------------------------- launch --------------------------------- */
extern "C" void kernel_launch(void* const* d_in, const int* in_sizes, int n_in,
                              void* d_out, int out_size)
{
    const int*   x   = (const int*)d_in[0];
    const float* we  = (const float*)d_in[1];
    const float* pe  = (const float*)d_in[2];
    const float* te  = (const float*)d_in[3];
    const float* lng = (const float*)d_in[4];
    const float* lnb = (const float*)d_in[5];
    const float* W   = (const float*)d_in[6];
    const float* bi  = (const float*)d_in[7];
    const float* Mm  = (const float*)d_in[8];
    const float* lw  = (const float*)d_in[9];
    const float* lb  = (const float*)d_in[10];
    float* out = (float*)d_out;

    __half *hA, *Xt, *Wh, *Mt;
    cudaGetSymbolAddress((void**)&hA, g_hA);
    cudaGetSymbolAddress((void**)&Xt, g_Xt);
    cudaGetSymbolAddress((void**)&Wh, g_W);
    cudaGetSymbolAddress((void**)&Mt, g_Mt);

    cudaFuncSetAttribute(gemm_dense_kernel<false>,
                         cudaFuncAttributeMaxDynamicSharedMemorySize, SMEM_DYN);
    cudaFuncSetAttribute(gemm_dense_kernel<true>,
                         cudaFuncAttributeMaxDynamicSharedMemorySize, SMEM_DYN);
    cudaFuncSetAttribute(gemm_mix_kernel,
                         cudaFuncAttributeMaxDynamicSharedMemorySize, SMEM_DYN);

    dim3 gd(HID / 128, ROWS / 128);       /* (6, 128)    */
    dim3 gm(SEQ / 128, HEADS, BATCH / 2); /* (4, 12, 16) */

    /* one-time conversions (dense0 hoisted before transpose for ncu) */
    embed_ln_kernel<<<ROWS, 256>>>(x, we, pe, te, lng, lnb, hA);
    cvt_hi_kernel<<<1024, 256>>>(W, Wh, LAYERS * HID * HID / 4);
    cvt_hi_kernel<<<144, 256>>>(lw, Wh + (size_t)LAYERS * HID * HID, HID * HID / 4);
    gemm_dense_kernel<false><<<gd, 128, SMEM_DYN>>>(hA, Wh, nullptr, Xt, nullptr);
    {
        dim3 tb(256), tg(SEQ / 32, SEQ / 32, LAYERS * HEADS / 4);
        transpose_cvt_kernel<<<tg, tb>>>(Mm, Mt);
    }
    gemm_mix_kernel<<<gm, 128, SMEM_DYN>>>(Xt, Mt, bi, hA);

    for (int l = 1; l < LAYERS; l++) {
        gemm_dense_kernel<false><<<gd, 128, SMEM_DYN>>>(
            hA, Wh + (size_t)l * HID * HID, nullptr, Xt, nullptr);
        gemm_mix_kernel<<<gm, 128, SMEM_DYN>>>(
            Xt, Mt + (size_t)l * HEADS * SEQ * SEQ,
            bi + (size_t)l * HID, hA);
    }
    gemm_dense_kernel<true><<<gd, 128, SMEM_DYN>>>(
        hA, Wh + (size_t)LAYERS * HID * HID, lb, nullptr, out);
}

// round 9
// speedup vs baseline: 6.7577x; 1.0257x over previous
#include <cuda_runtime.h>
#include <cuda_fp16.h>
#include <stdint.h>

#define SEQ    512
#define HID    768
#define HEADS  12
#define DH     64
#define LAYERS 12
#define BATCH  32
#define ROWS   (BATCH * SEQ)   /* 16384 */
#define LN_EPS 1e-12f

#define KT   32                 /* fp16 k per stage            */
#define RSE  40                 /* smem row stride, elements   */
#define RSB  80                 /* smem row stride, bytes      */
#define BUFB (128 * RSB)        /* one operand buffer: 10240 B */
#define STAGEB (2 * BUFB)       /* A, B: 20480 B               */
#define NSTAGE 3
#define OFF_A 0
#define OFF_B BUFB
#define SMEM_DYN (NSTAGE * STAGEB)   /* 61440 B (>= 128*136*2 fp16 stage) */

/* ------------------------- device scratch (static) ------------------------ */
__device__ __half g_hA[(size_t)ROWS * HID];
__device__ __half g_Xt[(size_t)ROWS * HID];   /* [B*HEADS*DH][SEQ] */
__device__ __half g_W[(size_t)(LAYERS + 1) * HID * HID];
__device__ __half g_Mt[(size_t)LAYERS * HEADS * SEQ * SEQ];

/* ------------------------------ PTX helpers ------------------------------ */
__device__ __forceinline__ uint32_t smem_u32(const void* p) {
    uint32_t a;
    asm("{ .reg .u64 t; cvta.to.shared.u64 t, %1; cvt.u32.u64 %0, t; }"
        : "=r"(a) : "l"(p));
    return a;
}
__device__ __forceinline__ void cpa16(uint32_t dst, const void* src) {
    asm volatile("cp.async.cg.shared.global [%0], [%1], 16;"
                 :: "r"(dst), "l"(src) : "memory");
}
__device__ __forceinline__ void cp_commit() {
    asm volatile("cp.async.commit_group;" ::: "memory");
}
__device__ __forceinline__ void cp_wait1() {
    asm volatile("cp.async.wait_group 1;" ::: "memory");
}
__device__ __forceinline__ void cp_wait0() {
    asm volatile("cp.async.wait_group 0;" ::: "memory");
}
__device__ __forceinline__ void ldm_x4(uint32_t* r, uint32_t addr) {
    asm volatile("ldmatrix.sync.aligned.m8n8.x4.shared.b16 {%0,%1,%2,%3}, [%4];"
                 : "=r"(r[0]), "=r"(r[1]), "=r"(r[2]), "=r"(r[3]) : "r"(addr));
}
__device__ __forceinline__ void mma16816(float* c, const uint32_t* a, const uint32_t* b) {
    asm volatile(
        "mma.sync.aligned.m16n8k16.row.col.f32.f16.f16.f32 "
        "{%0,%1,%2,%3},{%4,%5,%6,%7},{%8,%9},{%0,%1,%2,%3};"
        : "+f"(c[0]), "+f"(c[1]), "+f"(c[2]), "+f"(c[3])
        : "r"(a[0]), "r"(a[1]), "r"(a[2]), "r"(a[3]), "r"(b[0]), "r"(b[1]));
}

/* ------------------------------ stage loaders ----------------------------- */
/* 2 buffers x 512 16B chunks; 4 per thread (256 threads). buf = i>>1. */
__device__ __forceinline__ void stage_load_dense(
    uint32_t sm, const __half* A, const __half* W, int m0, int n0, int k0)
{
    int tid = threadIdx.x;
#pragma unroll
    for (int i = 0; i < 4; i++) {
        const int buf = i >> 1;
        int rem = tid + (i & 1) * 256;
        int row = rem >> 2;
        int c   = rem & 3;
        const __half* src = buf
            ? W + (size_t)(n0 + row) * HID + k0 + c * 8
            : A + (size_t)(m0 + row) * HID + k0 + c * 8;
        cpa16(sm + buf * BUFB + row * RSB + c * 16, src);
    }
}
__device__ __forceinline__ void stage_load_mix(
    uint32_t sm, const __half* M, const __half* X,
    int t0, int h, int b0, int s0)
{
    int tid = threadIdx.x;
#pragma unroll
    for (int i = 0; i < 4; i++) {
        const int buf = i >> 1;
        int rem = tid + (i & 1) * 256;
        int row = rem >> 2;
        int c   = rem & 3;
        const __half* src;
        if (buf == 0) {
            src = M + (size_t)(t0 + row) * SEQ + s0 + c * 8;
        } else {
            int bb = row >> 6, d = row & 63;
            size_t R = ((size_t)(b0 + bb) * HEADS + h) * DH + d;
            src = X + R * SEQ + s0 + c * 8;
        }
        cpa16(sm + buf * BUFB + row * RSB + c * 16, src);
    }
}

/* ------------------------------- MMA core -------------------------------- */
/* 8 warps, each computes a 32m x 64n tile; acc[16][4]. KT=32: 2 sub-k steps. */
__device__ __forceinline__ void compute_ktile(
    uint32_t sbase, float (*acc)[4], int wm, int wn, int lane)
{
    const int ar = lane & 15;
    const int ac = (lane >> 4) * 8;
    const int br = ((lane >> 4) << 3) + (lane & 7);
    const int bc = ((lane >> 3) & 1) * 8;
#pragma unroll
    for (int ks = 0; ks < 2; ks++) {
        uint32_t af[8];
#pragma unroll
        for (int mi = 0; mi < 2; mi++) {
            uint32_t off = ((wm * 32 + mi * 16 + ar) * RSE + ks * 16 + ac) * 2;
            ldm_x4(af + 4 * mi, sbase + OFF_A + off);
        }
#pragma unroll
        for (int nh = 0; nh < 2; nh++) {
            uint32_t bf[8];
#pragma unroll
            for (int g = 0; g < 2; g++) {
                uint32_t off = ((wn * 64 + nh * 32 + g * 16 + br) * RSE + ks * 16 + bc) * 2;
                ldm_x4(bf + 4 * g, sbase + OFF_B + off);
            }
#pragma unroll
            for (int mi = 0; mi < 2; mi++)
#pragma unroll
                for (int nj = 0; nj < 4; nj++)
                    mma16816(acc[mi * 8 + nh * 4 + nj], af + 4 * mi, bf + 2 * nj);
        }
    }
}

/* --------------------------- dense tensor GEMM ---------------------------- */
/* D[m,n] = sum_k A[m,k]*W[n,k].
   FINAL=false: write fp16 TRANSPOSED into Xt[(b*HEADS+h)*DH+d][s] via fp16 stage.
   FINAL=true : direct reg->global f32 + bias, no staging. */
template <bool FINAL>
__global__ void __launch_bounds__(256, 2) gemm_dense_kernel(
    const __half* __restrict__ A, const __half* __restrict__ W,
    const float* __restrict__ bias,
    __half* __restrict__ Oh, float* __restrict__ Of)
{
    extern __shared__ __align__(16) char smem[];
    uint32_t sb = smem_u32(smem);
    int tid = threadIdx.x, lane = tid & 31, wid = tid >> 5;
    int wm = wid & 3, wn = wid >> 2;
    int n0 = blockIdx.x * 128, m0 = blockIdx.y * 128;

    float acc[16][4];
#pragma unroll
    for (int i = 0; i < 16; i++)
#pragma unroll
        for (int j = 0; j < 4; j++) acc[i][j] = 0.f;

    const int NK = HID / KT;   /* 24 */
    stage_load_dense(sb,          A, W, m0, n0, 0);  cp_commit();
    stage_load_dense(sb + STAGEB, A, W, m0, n0, KT); cp_commit();

    for (int i = 0; i < NK; i++) {
        if (i + 1 < NK) cp_wait1(); else cp_wait0();
        __syncthreads();
        if (i + 2 < NK) {
            stage_load_dense(sb + ((i + 2) % NSTAGE) * STAGEB, A, W, m0, n0, (i + 2) * KT);
            cp_commit();
        }
        compute_ktile(sb + (i % NSTAGE) * STAGEB, acc, wm, wn, lane);
    }

    if (FINAL) {
        /* direct reg -> global f32 + bias (no staging) */
        const int r0 = wm * 32 + (lane >> 2);
        const int c0 = wn * 64 + (lane & 3) * 2;
#pragma unroll
        for (int mi = 0; mi < 2; mi++)
#pragma unroll
            for (int njj = 0; njj < 8; njj++) {
                int m = m0 + r0 + mi * 16;
                int n = n0 + c0 + (njj >> 2) * 32 + (njj & 3) * 8;
                const float* ac = acc[mi * 8 + njj];
                float b0v = bias[n], b1v = bias[n + 1];
                float2 v0 = make_float2(ac[0] + b0v, ac[1] + b1v);
                float2 v1 = make_float2(ac[2] + b0v, ac[3] + b1v);
                *(float2*)&Of[(size_t)m * HID + n]       = v0;
                *(float2*)&Of[(size_t)(m + 8) * HID + n] = v1;
            }
        return;
    }

    /* transposed fp16 write via fp16 stage [128][136] */
    __syncthreads();
    __half* hst = (__half*)smem;
#pragma unroll
    for (int mi = 0; mi < 2; mi++)
#pragma unroll
        for (int njj = 0; njj < 8; njj++) {
            int r  = wm * 32 + mi * 16 + (lane >> 2);
            int cn = wn * 64 + (njj >> 2) * 32 + (njj & 3) * 8 + (lane & 3) * 2;
            const float* ac = acc[mi * 8 + njj];
            *(half2*)&hst[r * 136 + cn]       = __floats2half2_rn(ac[0], ac[1]);
            *(half2*)&hst[(r + 8) * 136 + cn] = __floats2half2_rn(ac[2], ac[3]);
        }
    __syncthreads();

    /* 256 threads: thread -> one n-col, half the s range */
    int n  = tid & 127;
    int sh = tid >> 7;
    int ng = n0 + n;
    int h  = ng >> 6, d = ng & 63;
    int b  = m0 >> 9;
    int s  = (m0 & 511) + sh * 64;
    size_t R = ((size_t)b * HEADS + h) * DH + d;
    __half* dh = Oh + R * SEQ + s;
#pragma unroll
    for (int q = 0; q < 8; q++) {
        __align__(16) __half hv[8];
#pragma unroll
        for (int j = 0; j < 8; j++)
            hv[j] = hst[(sh * 64 + q * 8 + j) * 136 + n];
        *(uint4*)(dh + q * 8) = *(const uint4*)hv;
    }
}

/* ---------------------------- mix tensor GEMM ----------------------------- */
/* Out[b0+bb, t0+t, h*64+d] = relu( sum_s Mt[h,t,s] * X[b,s,h*64+d] + bias ),
   A = Mt (row-major t x s), B = Xt (row-major n x s).  Direct reg epilogue. */
__global__ void __launch_bounds__(256, 2) gemm_mix_kernel(
    const __half* __restrict__ X, const __half* __restrict__ Mt,
    const float* __restrict__ bias, __half* __restrict__ Oh)
{
    extern __shared__ __align__(16) char smem[];
    uint32_t sb = smem_u32(smem);
    int tid = threadIdx.x, lane = tid & 31, wid = tid >> 5;
    int wm = wid & 3, wn = wid >> 2;
    int t0 = blockIdx.x * 128;
    int h  = blockIdx.y;
    int b0 = blockIdx.z * 2;

    const __half* Mh = Mt + (size_t)h * SEQ * SEQ;

    float acc[16][4];
#pragma unroll
    for (int i = 0; i < 16; i++)
#pragma unroll
        for (int j = 0; j < 4; j++) acc[i][j] = 0.f;

    const int NK = SEQ / KT;   /* 16 */
    stage_load_mix(sb,          Mh, X, t0, h, b0, 0);  cp_commit();
    stage_load_mix(sb + STAGEB, Mh, X, t0, h, b0, KT); cp_commit();

    for (int i = 0; i < NK; i++) {
        if (i + 1 < NK) cp_wait1(); else cp_wait0();
        __syncthreads();
        if (i + 2 < NK) {
            stage_load_mix(sb + ((i + 2) % NSTAGE) * STAGEB, Mh, X, t0, h, b0, (i + 2) * KT);
            cp_commit();
        }
        compute_ktile(sb + (i % NSTAGE) * STAGEB, acc, wm, wn, lane);
    }

    /* direct reg -> global: bias + relu + cvt, half2 stores */
    const int r0 = wm * 32 + (lane >> 2);
    const int c0 = wn * 64 + (lane & 3) * 2;
#pragma unroll
    for (int mi = 0; mi < 2; mi++)
#pragma unroll
        for (int njj = 0; njj < 8; njj++) {
            int m = t0 + r0 + mi * 16;
            int n = c0 + (njj >> 2) * 32 + (njj & 3) * 8;   /* 0..127 */
            int bb = n >> 6, d = n & 63;
            int col = h * DH + d;
            const float* ac = acc[mi * 8 + njj];
            float b0v = bias[col], b1v = bias[col + 1];
            size_t rowg = (size_t)(b0 + bb) * SEQ + m;
            half2 v0 = __floats2half2_rn(fmaxf(ac[0] + b0v, 0.f), fmaxf(ac[1] + b1v, 0.f));
            half2 v1 = __floats2half2_rn(fmaxf(ac[2] + b0v, 0.f), fmaxf(ac[3] + b1v, 0.f));
            *(half2*)&Oh[rowg * HID + col]       = v0;
            *(half2*)&Oh[(rowg + 8) * HID + col] = v1;
        }
}

/* --------------------------- conversion kernels --------------------------- */
/* vectorized f32 -> f16: 4 elements per thread iteration */
__global__ void __launch_bounds__(256) cvt_hi_kernel(
    const float* __restrict__ s, __half* __restrict__ dh, int n4)
{
    for (int i = blockIdx.x * 256 + threadIdx.x; i < n4; i += gridDim.x * 256) {
        float4 v = ((const float4*)s)[i];
        __align__(8) __half o[4];
        o[0] = __float2half_rn(v.x); o[1] = __float2half_rn(v.y);
        o[2] = __float2half_rn(v.z); o[3] = __float2half_rn(v.w);
        ((uint2*)dh)[i] = *(const uint2*)o;
    }
}

/* Mt[l,h,t,s] = M[l,h,s,t]; 32x32 transpose, vectorized 8B stores, z-batch 4. */
__global__ void __launch_bounds__(256) transpose_cvt_kernel(
    const float* __restrict__ M, __half* __restrict__ th)
{
    __shared__ float tile[32][33];
    int s0 = blockIdx.x * 32, t0 = blockIdx.y * 32;
    int tx = threadIdx.x & 31, ty = threadIdx.x >> 5;   /* (32,8) */
    int wt = threadIdx.x >> 3;          /* t index 0..31 */
    int sq = (threadIdx.x & 7) * 4;     /* s quad base   */
#pragma unroll 1
    for (int zz = 0; zz < 4; zz++) {
        int z = blockIdx.z * 4 + zz;
        const float* src = M + (size_t)z * SEQ * SEQ;
        size_t ob = (size_t)z * SEQ * SEQ;
#pragma unroll
        for (int i = ty; i < 32; i += 8)
            tile[i][tx] = src[(size_t)(s0 + i) * SEQ + t0 + tx];
        __syncthreads();
        __align__(8) __half o[4];
#pragma unroll
        for (int j = 0; j < 4; j++)
            o[j] = __float2half_rn(tile[sq + j][wt]);
        *(uint2*)&th[ob + (size_t)(t0 + wt) * SEQ + s0 + sq] = *(const uint2*)o;
        __syncthreads();
    }
}

__global__ void __launch_bounds__(256) embed_ln_kernel(
    const int* __restrict__ x,
    const float* __restrict__ we, const float* __restrict__ pe,
    const float* __restrict__ te,
    const float* __restrict__ g, const float* __restrict__ beta,
    __half* __restrict__ oh)
{
    int row = blockIdx.x;
    int s   = row & (SEQ - 1);
    int tok = x[row];
    const float* w = we + (size_t)tok * HID;
    const float* p = pe + (size_t)s * HID;

    float v[3];
    float sum = 0.f;
#pragma unroll
    for (int i = 0; i < 3; i++) {
        int c = threadIdx.x + i * 256;
        v[i] = w[c] + p[c] + te[c];
        sum += v[i];
    }

    __shared__ float red[8];
    __shared__ float s_mu, s_rs;
#pragma unroll
    for (int o = 16; o > 0; o >>= 1) sum += __shfl_down_sync(0xffffffffu, sum, o);
    if ((threadIdx.x & 31) == 0) red[threadIdx.x >> 5] = sum;
    __syncthreads();
    if (threadIdx.x == 0) {
        float t = 0.f;
#pragma unroll
        for (int i = 0; i < 8; i++) t += red[i];
        s_mu = t * (1.f / HID);
    }
    __syncthreads();
    float mu = s_mu;

    float sq = 0.f;
#pragma unroll
    for (int i = 0; i < 3; i++) { float d = v[i] - mu; sq += d * d; }
#pragma unroll
    for (int o = 16; o > 0; o >>= 1) sq += __shfl_down_sync(0xffffffffu, sq, o);
    if ((threadIdx.x & 31) == 0) red[threadIdx.x >> 5] = sq;
    __syncthreads();
    if (threadIdx.x == 0) {
        float t = 0.f;
#pragma unroll
        for (int i = 0; i < 8; i++) t += red[i];
        s_rs = rsqrtf(t * (1.f / HID) + LN_EPS);
    }
    __syncthreads();
    float rs = s_rs;

#pragma unroll
    for (int i = 0; i < 3; i++) {
        int c = threadIdx.x + i * 256;
        float val = (v[i] - mu) * rs * g[c] + beta[c];
        oh[(size_t)row * HID + c] = __float2half_rn(val);
    }
}

/* --------------------------------- launch --------------------------------- */
extern "C" void kernel_launch(void* const* d_in, const int* in_sizes, int n_in,
                              void* d_out, int out_size)
{
    const int*   x   = (const int*)d_in[0];
    const float* we  = (const float*)d_in[1];
    const float* pe  = (const float*)d_in[2];
    const float* te  = (const float*)d_in[3];
    const float* lng = (const float*)d_in[4];
    const float* lnb = (const float*)d_in[5];
    const float* W   = (const float*)d_in[6];
    const float* bi  = (const float*)d_in[7];
    const float* Mm  = (const float*)d_in[8];
    const float* lw  = (const float*)d_in[9];
    const float* lb  = (const float*)d_in[10];
    float* out = (float*)d_out;

    __half *hA, *Xt, *Wh, *Mt;
    cudaGetSymbolAddress((void**)&hA, g_hA);
    cudaGetSymbolAddress((void**)&Xt, g_Xt);
    cudaGetSymbolAddress((void**)&Wh, g_W);
    cudaGetSymbolAddress((void**)&Mt, g_Mt);

    cudaFuncSetAttribute(gemm_dense_kernel<false>,
                         cudaFuncAttributeMaxDynamicSharedMemorySize, SMEM_DYN);
    cudaFuncSetAttribute(gemm_dense_kernel<true>,
                         cudaFuncAttributeMaxDynamicSharedMemorySize, SMEM_DYN);
    cudaFuncSetAttribute(gemm_mix_kernel,
                         cudaFuncAttributeMaxDynamicSharedMemorySize, SMEM_DYN);

    dim3 gd(HID / 128, ROWS / 128);       /* (6, 128)    */
    dim3 gm(SEQ / 128, HEADS, BATCH / 2); /* (4, 12, 16) */

    /* one-time conversions (dense0 hoisted before transpose for ncu) */
    embed_ln_kernel<<<ROWS, 256>>>(x, we, pe, te, lng, lnb, hA);
    cvt_hi_kernel<<<1024, 256>>>(W, Wh, LAYERS * HID * HID / 4);
    cvt_hi_kernel<<<144, 256>>>(lw, Wh + (size_t)LAYERS * HID * HID, HID * HID / 4);
    gemm_dense_kernel<false><<<gd, 256, SMEM_DYN>>>(hA, Wh, nullptr, Xt, nullptr);
    {
        dim3 tb(256), tg(SEQ / 32, SEQ / 32, LAYERS * HEADS / 4);
        transpose_cvt_kernel<<<tg, tb>>>(Mm, Mt);
    }
    gemm_mix_kernel<<<gm, 256, SMEM_DYN>>>(Xt, Mt, bi, hA);

    for (int l = 1; l < LAYERS; l++) {
        gemm_dense_kernel<false><<<gd, 256, SMEM_DYN>>>(
            hA, Wh + (size_t)l * HID * HID, nullptr, Xt, nullptr);
        gemm_mix_kernel<<<gm, 256, SMEM_DYN>>>(
            Xt, Mt + (size_t)l * HEADS * SEQ * SEQ,
            bi + (size_t)l * HID, hA);
    }
    gemm_dense_kernel<true><<<gd, 256, SMEM_DYN>>>(
        hA, Wh + (size_t)LAYERS * HID * HID, lb, nullptr, out);
}

// round 10
// speedup vs baseline: 6.8821x; 1.0184x over previous
#include <cuda_runtime.h>
#include <cuda_fp16.h>
#include <stdint.h>

#define SEQ    512
#define HID    768
#define HEADS  12
#define DH     64
#define LAYERS 12
#define BATCH  32
#define ROWS   (BATCH * SEQ)   /* 16384 */
#define LN_EPS 1e-12f

#define KT   32                 /* fp16 k per stage            */
#define RSE  40                 /* smem row stride, elements   */
#define RSB  80                 /* smem row stride, bytes      */
#define BUFB (128 * RSB)        /* one operand buffer: 10240 B */
#define STAGEB (2 * BUFB)       /* A, B: 20480 B               */
#define NSTAGE 4
#define OFF_A 0
#define OFF_B BUFB
#define SMEM_DYN (NSTAGE * STAGEB)   /* 81920 B (>= 128*136*2 fp16 stage) */

/* ------------------------- device scratch (static) ------------------------ */
__device__ __half g_hA[(size_t)ROWS * HID];
__device__ __half g_Xt[(size_t)ROWS * HID];   /* [B*HEADS*DH][SEQ] */
__device__ __half g_W[(size_t)(LAYERS + 1) * HID * HID];
__device__ __half g_Mt[(size_t)LAYERS * HEADS * SEQ * SEQ];

/* ------------------------------ PTX helpers ------------------------------ */
__device__ __forceinline__ uint32_t smem_u32(const void* p) {
    uint32_t a;
    asm("{ .reg .u64 t; cvta.to.shared.u64 t, %1; cvt.u32.u64 %0, t; }"
        : "=r"(a) : "l"(p));
    return a;
}
__device__ __forceinline__ void cpa16(uint32_t dst, const void* src) {
    asm volatile("cp.async.cg.shared.global [%0], [%1], 16;"
                 :: "r"(dst), "l"(src) : "memory");
}
__device__ __forceinline__ void cp_commit() {
    asm volatile("cp.async.commit_group;" ::: "memory");
}
__device__ __forceinline__ void cp_wait1() {
    asm volatile("cp.async.wait_group 1;" ::: "memory");
}
__device__ __forceinline__ void cp_wait0() {
    asm volatile("cp.async.wait_group 0;" ::: "memory");
}
__device__ __forceinline__ void ldm_x4(uint32_t* r, uint32_t addr) {
    asm volatile("ldmatrix.sync.aligned.m8n8.x4.shared.b16 {%0,%1,%2,%3}, [%4];"
                 : "=r"(r[0]), "=r"(r[1]), "=r"(r[2]), "=r"(r[3]) : "r"(addr));
}
__device__ __forceinline__ void mma16816(float* c, const uint32_t* a, const uint32_t* b) {
    asm volatile(
        "mma.sync.aligned.m16n8k16.row.col.f32.f16.f16.f32 "
        "{%0,%1,%2,%3},{%4,%5,%6,%7},{%8,%9},{%0,%1,%2,%3};"
        : "+f"(c[0]), "+f"(c[1]), "+f"(c[2]), "+f"(c[3])
        : "r"(a[0]), "r"(a[1]), "r"(a[2]), "r"(a[3]), "r"(b[0]), "r"(b[1]));
}

/* ------------------------------ stage loaders ----------------------------- */
/* 2 buffers x 512 16B chunks; 4 per thread (256 threads). buf = i>>1. */
__device__ __forceinline__ void stage_load_dense(
    uint32_t sm, const __half* A, const __half* W, int m0, int n0, int k0)
{
    int tid = threadIdx.x;
#pragma unroll
    for (int i = 0; i < 4; i++) {
        const int buf = i >> 1;
        int rem = tid + (i & 1) * 256;
        int row = rem >> 2;
        int c   = rem & 3;
        const __half* src = buf
            ? W + (size_t)(n0 + row) * HID + k0 + c * 8
            : A + (size_t)(m0 + row) * HID + k0 + c * 8;
        cpa16(sm + buf * BUFB + row * RSB + c * 16, src);
    }
}
__device__ __forceinline__ void stage_load_mix(
    uint32_t sm, const __half* M, const __half* X,
    int t0, int h, int b0, int s0)
{
    int tid = threadIdx.x;
#pragma unroll
    for (int i = 0; i < 4; i++) {
        const int buf = i >> 1;
        int rem = tid + (i & 1) * 256;
        int row = rem >> 2;
        int c   = rem & 3;
        const __half* src;
        if (buf == 0) {
            src = M + (size_t)(t0 + row) * SEQ + s0 + c * 8;
        } else {
            int bb = row >> 6, d = row & 63;
            size_t R = ((size_t)(b0 + bb) * HEADS + h) * DH + d;
            src = X + R * SEQ + s0 + c * 8;
        }
        cpa16(sm + buf * BUFB + row * RSB + c * 16, src);
    }
}

/* ------------------------------- MMA core -------------------------------- */
/* 8 warps, each 32m x 64n; acc[16][4].  Fragment load / MMA split so the
   cp.async prefetch can be issued between them. */
__device__ __forceinline__ void load_frags(
    uint32_t sbase, int ks, int wm, int wn, int lane,
    uint32_t* af, uint32_t* bf)
{
    const int ar = lane & 15;
    const int ac = (lane >> 4) * 8;
    const int br = ((lane >> 4) << 3) + (lane & 7);
    const int bc = ((lane >> 3) & 1) * 8;
#pragma unroll
    for (int mi = 0; mi < 2; mi++) {
        uint32_t off = ((wm * 32 + mi * 16 + ar) * RSE + ks * 16 + ac) * 2;
        ldm_x4(af + 4 * mi, sbase + OFF_A + off);
    }
#pragma unroll
    for (int nh = 0; nh < 2; nh++)
#pragma unroll
        for (int g = 0; g < 2; g++) {
            uint32_t off = ((wn * 64 + nh * 32 + g * 16 + br) * RSE + ks * 16 + bc) * 2;
            ldm_x4(bf + nh * 8 + 4 * g, sbase + OFF_B + off);
        }
}
__device__ __forceinline__ void mma_frags(
    float (*acc)[4], const uint32_t* af, const uint32_t* bf)
{
#pragma unroll
    for (int nh = 0; nh < 2; nh++)
#pragma unroll
        for (int mi = 0; mi < 2; mi++)
#pragma unroll
            for (int nj = 0; nj < 4; nj++)
                mma16816(acc[mi * 8 + nh * 4 + nj], af + 4 * mi, bf + nh * 8 + 2 * nj);
}

/* --------------------------- dense tensor GEMM ---------------------------- */
template <bool FINAL>
__global__ void __launch_bounds__(256, 2) gemm_dense_kernel(
    const __half* __restrict__ A, const __half* __restrict__ W,
    const float* __restrict__ bias,
    __half* __restrict__ Oh, float* __restrict__ Of)
{
    extern __shared__ __align__(16) char smem[];
    uint32_t sb = smem_u32(smem);
    int tid = threadIdx.x, lane = tid & 31, wid = tid >> 5;
    int wm = wid & 3, wn = wid >> 2;
    int n0 = blockIdx.x * 128, m0 = blockIdx.y * 128;

    float acc[16][4];
#pragma unroll
    for (int i = 0; i < 16; i++)
#pragma unroll
        for (int j = 0; j < 4; j++) acc[i][j] = 0.f;

    const int NK = HID / KT;   /* 24 */
    stage_load_dense(sb,          A, W, m0, n0, 0);  cp_commit();
    stage_load_dense(sb + STAGEB, A, W, m0, n0, KT); cp_commit();

    for (int i = 0; i < NK; i++) {
        if (i + 1 < NK) cp_wait1(); else cp_wait0();
        if ((i & 1) == 0) __syncthreads();
        uint32_t sbase = sb + (i & 3) * STAGEB;
        uint32_t af[8], bf[16];
        load_frags(sbase, 0, wm, wn, lane, af, bf);
        if (i + 2 < NK) {
            stage_load_dense(sb + ((i + 2) & 3) * STAGEB, A, W, m0, n0, (i + 2) * KT);
            cp_commit();
        }
        mma_frags(acc, af, bf);
        load_frags(sbase, 1, wm, wn, lane, af, bf);
        mma_frags(acc, af, bf);
    }

    if (FINAL) {
        const int r0 = wm * 32 + (lane >> 2);
        const int c0 = wn * 64 + (lane & 3) * 2;
#pragma unroll
        for (int mi = 0; mi < 2; mi++)
#pragma unroll
            for (int njj = 0; njj < 8; njj++) {
                int m = m0 + r0 + mi * 16;
                int n = n0 + c0 + (njj >> 2) * 32 + (njj & 3) * 8;
                const float* ac = acc[mi * 8 + njj];
                float b0v = bias[n], b1v = bias[n + 1];
                float2 v0 = make_float2(ac[0] + b0v, ac[1] + b1v);
                float2 v1 = make_float2(ac[2] + b0v, ac[3] + b1v);
                *(float2*)&Of[(size_t)m * HID + n]       = v0;
                *(float2*)&Of[(size_t)(m + 8) * HID + n] = v1;
            }
        return;
    }

    /* transposed fp16 write via fp16 stage [128][136] */
    __syncthreads();
    __half* hst = (__half*)smem;
#pragma unroll
    for (int mi = 0; mi < 2; mi++)
#pragma unroll
        for (int njj = 0; njj < 8; njj++) {
            int r  = wm * 32 + mi * 16 + (lane >> 2);
            int cn = wn * 64 + (njj >> 2) * 32 + (njj & 3) * 8 + (lane & 3) * 2;
            const float* ac = acc[mi * 8 + njj];
            *(half2*)&hst[r * 136 + cn]       = __floats2half2_rn(ac[0], ac[1]);
            *(half2*)&hst[(r + 8) * 136 + cn] = __floats2half2_rn(ac[2], ac[3]);
        }
    __syncthreads();

    int n  = tid & 127;
    int sh = tid >> 7;
    int ng = n0 + n;
    int h  = ng >> 6, d = ng & 63;
    int b  = m0 >> 9;
    int s  = (m0 & 511) + sh * 64;
    size_t R = ((size_t)b * HEADS + h) * DH + d;
    __half* dh = Oh + R * SEQ + s;
#pragma unroll
    for (int q = 0; q < 8; q++) {
        __align__(16) __half hv[8];
#pragma unroll
        for (int j = 0; j < 8; j++)
            hv[j] = hst[(sh * 64 + q * 8 + j) * 136 + n];
        *(uint4*)(dh + q * 8) = *(const uint4*)hv;
    }
}

/* ---------------------------- mix tensor GEMM ----------------------------- */
__global__ void __launch_bounds__(256, 2) gemm_mix_kernel(
    const __half* __restrict__ X, const __half* __restrict__ Mt,
    const float* __restrict__ bias, __half* __restrict__ Oh)
{
    extern __shared__ __align__(16) char smem[];
    uint32_t sb = smem_u32(smem);
    int tid = threadIdx.x, lane = tid & 31, wid = tid >> 5;
    int wm = wid & 3, wn = wid >> 2;
    int t0 = blockIdx.x * 128;
    int h  = blockIdx.y;
    int b0 = blockIdx.z * 2;

    const __half* Mh = Mt + (size_t)h * SEQ * SEQ;

    float acc[16][4];
#pragma unroll
    for (int i = 0; i < 16; i++)
#pragma unroll
        for (int j = 0; j < 4; j++) acc[i][j] = 0.f;

    const int NK = SEQ / KT;   /* 16 */
    stage_load_mix(sb,          Mh, X, t0, h, b0, 0);  cp_commit();
    stage_load_mix(sb + STAGEB, Mh, X, t0, h, b0, KT); cp_commit();

    for (int i = 0; i < NK; i++) {
        if (i + 1 < NK) cp_wait1(); else cp_wait0();
        if ((i & 1) == 0) __syncthreads();
        uint32_t sbase = sb + (i & 3) * STAGEB;
        uint32_t af[8], bf[16];
        load_frags(sbase, 0, wm, wn, lane, af, bf);
        if (i + 2 < NK) {
            stage_load_mix(sb + ((i + 2) & 3) * STAGEB, Mh, X, t0, h, b0, (i + 2) * KT);
            cp_commit();
        }
        mma_frags(acc, af, bf);
        load_frags(sbase, 1, wm, wn, lane, af, bf);
        mma_frags(acc, af, bf);
    }

    /* direct reg -> global: bias + relu + cvt, half2 stores */
    const int r0 = wm * 32 + (lane >> 2);
    const int c0 = wn * 64 + (lane & 3) * 2;
#pragma unroll
    for (int mi = 0; mi < 2; mi++)
#pragma unroll
        for (int njj = 0; njj < 8; njj++) {
            int m = t0 + r0 + mi * 16;
            int n = c0 + (njj >> 2) * 32 + (njj & 3) * 8;   /* 0..127 */
            int bb = n >> 6, d = n & 63;
            int col = h * DH + d;
            const float* ac = acc[mi * 8 + njj];
            float b0v = bias[col], b1v = bias[col + 1];
            size_t rowg = (size_t)(b0 + bb) * SEQ + m;
            half2 v0 = __floats2half2_rn(fmaxf(ac[0] + b0v, 0.f), fmaxf(ac[1] + b1v, 0.f));
            half2 v1 = __floats2half2_rn(fmaxf(ac[2] + b0v, 0.f), fmaxf(ac[3] + b1v, 0.f));
            *(half2*)&Oh[rowg * HID + col]       = v0;
            *(half2*)&Oh[(rowg + 8) * HID + col] = v1;
        }
}

/* --------------------------- conversion kernels --------------------------- */
__global__ void __launch_bounds__(256) cvt_hi_kernel(
    const float* __restrict__ s, __half* __restrict__ dh, int n4)
{
    for (int i = blockIdx.x * 256 + threadIdx.x; i < n4; i += gridDim.x * 256) {
        float4 v = ((const float4*)s)[i];
        __align__(8) __half o[4];
        o[0] = __float2half_rn(v.x); o[1] = __float2half_rn(v.y);
        o[2] = __float2half_rn(v.z); o[3] = __float2half_rn(v.w);
        ((uint2*)dh)[i] = *(const uint2*)o;
    }
}

/* Mt[l,h,t,s] = M[l,h,s,t]; 64s x 32t tiles (128B store rows), z-batch 4. */
__global__ void __launch_bounds__(256) transpose_cvt_kernel(
    const float* __restrict__ M, __half* __restrict__ th)
{
    __shared__ float tile[64][33];
    int s0 = blockIdx.x * 64, t0 = blockIdx.y * 32;
    int tx = threadIdx.x & 31, ty = threadIdx.x >> 5;
    int wt = threadIdx.x >> 3;          /* t index 0..31 */
    int sq = (threadIdx.x & 7) * 8;     /* s octet base  */
#pragma unroll 1
    for (int zz = 0; zz < 4; zz++) {
        int z = blockIdx.z * 4 + zz;
        const float* src = M + (size_t)z * SEQ * SEQ;
        size_t ob = (size_t)z * SEQ * SEQ;
#pragma unroll
        for (int i = ty; i < 64; i += 8)
            tile[i][tx] = src[(size_t)(s0 + i) * SEQ + t0 + tx];
        __syncthreads();
        __align__(16) __half o[8];
#pragma unroll
        for (int j = 0; j < 8; j++)
            o[j] = __float2half_rn(tile[sq + j][wt]);
        *(uint4*)&th[ob + (size_t)(t0 + wt) * SEQ + s0 + sq] = *(const uint4*)o;
        __syncthreads();
    }
}

__global__ void __launch_bounds__(256) embed_ln_kernel(
    const int* __restrict__ x,
    const float* __restrict__ we, const float* __restrict__ pe,
    const float* __restrict__ te,
    const float* __restrict__ g, const float* __restrict__ beta,
    __half* __restrict__ oh)
{
    int row = blockIdx.x;
    int s   = row & (SEQ - 1);
    int tok = x[row];
    const float* w = we + (size_t)tok * HID;
    const float* p = pe + (size_t)s * HID;

    float v[3];
    float sum = 0.f;
#pragma unroll
    for (int i = 0; i < 3; i++) {
        int c = threadIdx.x + i * 256;
        v[i] = w[c] + p[c] + te[c];
        sum += v[i];
    }

    __shared__ float red[8];
    __shared__ float s_mu, s_rs;
#pragma unroll
    for (int o = 16; o > 0; o >>= 1) sum += __shfl_down_sync(0xffffffffu, sum, o);
    if ((threadIdx.x & 31) == 0) red[threadIdx.x >> 5] = sum;
    __syncthreads();
    if (threadIdx.x == 0) {
        float t = 0.f;
#pragma unroll
        for (int i = 0; i < 8; i++) t += red[i];
        s_mu = t * (1.f / HID);
    }
    __syncthreads();
    float mu = s_mu;

    float sq = 0.f;
#pragma unroll
    for (int i = 0; i < 3; i++) { float d = v[i] - mu; sq += d * d; }
#pragma unroll
    for (int o = 16; o > 0; o >>= 1) sq += __shfl_down_sync(0xffffffffu, sq, o);
    if ((threadIdx.x & 31) == 0) red[threadIdx.x >> 5] = sq;
    __syncthreads();
    if (threadIdx.x == 0) {
        float t = 0.f;
#pragma unroll
        for (int i = 0; i < 8; i++) t += red[i];
        s_rs = rsqrtf(t * (1.f / HID) + LN_EPS);
    }
    __syncthreads();
    float rs = s_rs;

#pragma unroll
    for (int i = 0; i < 3; i++) {
        int c = threadIdx.x + i * 256;
        float val = (v[i] - mu) * rs * g[c] + beta[c];
        oh[(size_t)row * HID + c] = __float2half_rn(val);
    }
}

/* --------------------------------- launch --------------------------------- */
extern "C" void kernel_launch(void* const* d_in, const int* in_sizes, int n_in,
                              void* d_out, int out_size)
{
    const int*   x   = (const int*)d_in[0];
    const float* we  = (const float*)d_in[1];
    const float* pe  = (const float*)d_in[2];
    const float* te  = (const float*)d_in[3];
    const float* lng = (const float*)d_in[4];
    const float* lnb = (const float*)d_in[5];
    const float* W   = (const float*)d_in[6];
    const float* bi  = (const float*)d_in[7];
    const float* Mm  = (const float*)d_in[8];
    const float* lw  = (const float*)d_in[9];
    const float* lb  = (const float*)d_in[10];
    float* out = (float*)d_out;

    __half *hA, *Xt, *Wh, *Mt;
    cudaGetSymbolAddress((void**)&hA, g_hA);
    cudaGetSymbolAddress((void**)&Xt, g_Xt);
    cudaGetSymbolAddress((void**)&Wh, g_W);
    cudaGetSymbolAddress((void**)&Mt, g_Mt);

    cudaFuncSetAttribute(gemm_dense_kernel<false>,
                         cudaFuncAttributeMaxDynamicSharedMemorySize, SMEM_DYN);
    cudaFuncSetAttribute(gemm_dense_kernel<true>,
                         cudaFuncAttributeMaxDynamicSharedMemorySize, SMEM_DYN);
    cudaFuncSetAttribute(gemm_mix_kernel,
                         cudaFuncAttributeMaxDynamicSharedMemorySize, SMEM_DYN);

    dim3 gd(HID / 128, ROWS / 128);       /* (6, 128)    */
    dim3 gm(SEQ / 128, HEADS, BATCH / 2); /* (4, 12, 16) */

    /* one-time conversions */
    embed_ln_kernel<<<ROWS, 256>>>(x, we, pe, te, lng, lnb, hA);
    cvt_hi_kernel<<<1024, 256>>>(W, Wh, LAYERS * HID * HID / 4);
    cvt_hi_kernel<<<144, 256>>>(lw, Wh + (size_t)LAYERS * HID * HID, HID * HID / 4);
    gemm_dense_kernel<false><<<gd, 256, SMEM_DYN>>>(hA, Wh, nullptr, Xt, nullptr);
    {
        dim3 tb(256), tg(SEQ / 64, SEQ / 32, LAYERS * HEADS / 4);
        transpose_cvt_kernel<<<tg, tb>>>(Mm, Mt);
    }
    gemm_mix_kernel<<<gm, 256, SMEM_DYN>>>(Xt, Mt, bi, hA);

    for (int l = 1; l < LAYERS; l++) {
        gemm_dense_kernel<false><<<gd, 256, SMEM_DYN>>>(
            hA, Wh + (size_t)l * HID * HID, nullptr, Xt, nullptr);
        gemm_mix_kernel<<<gm, 256, SMEM_DYN>>>(
            Xt, Mt + (size_t)l * HEADS * SEQ * SEQ,
            bi + (size_t)l * HID, hA);
    }
    gemm_dense_kernel<true><<<gd, 256, SMEM_DYN>>>(
        hA, Wh + (size_t)LAYERS * HID * HID, lb, nullptr, out);
}